// round 1
// baseline (speedup 1.0000x reference)
#include <cuda_runtime.h>
#include <math.h>

#define BT    4096     // B*T token rows
#define TSEQ  2048
#define NHEADS 16
#define DM    2048
#define DQK   192
#define DV    128
#define ATT_SCALE 0.07216878364870323f   // 1/sqrt(192)

// ---------------- scratch (static device globals; no allocation) ----------------
__device__ float g_qproj[BT * DM];          // x @ w_q^T           [4096,2048]
__device__ float g_qrot [BT * 1024];        // x @ w_q_rot^T       [4096,1024] (roped in place)
__device__ float g_dkv  [BT * 512];         // x @ w_dkv^T         [4096,512]
__device__ float g_ukv  [BT * 4096];        // dkv @ w_ukv^T       [4096,4096] (k|v interleaved per head)
__device__ float g_krot [BT * 64];          // x @ w_k_rot^T       [4096,64]  (roped in place)
__device__ float g_attn [BT * DM];          // attention output    [4096,2048]

// ---------------- NT GEMM: C[M,N] = A[M,K] * B[N,K]^T (all row-major) ----------------
// 128x128 block tile, BK=16, 8x8 microtile, 256 threads, gmem->reg prefetch double buffer.
__global__ __launch_bounds__(256) void gemm_nt(const float* __restrict__ A,
                                               const float* __restrict__ B,
                                               float* __restrict__ C,
                                               int M, int N, int K) {
    __shared__ __align__(16) float As[16][132];
    __shared__ __align__(16) float Bs[16][132];

    const int tid = threadIdx.x;
    const int m0 = blockIdx.y * 128;
    const int n0 = blockIdx.x * 128;
    const int tx = tid & 15;       // 0..15 (n)
    const int ty = tid >> 4;       // 0..15 (m)
    const int lrow = tid >> 2;     // 0..63
    const int lc4  = (tid & 3) << 2;

    float acc[8][8];
#pragma unroll
    for (int i = 0; i < 8; ++i)
#pragma unroll
        for (int j = 0; j < 8; ++j) acc[i][j] = 0.f;

    const float* Arow0 = A + (size_t)(m0 + lrow) * K + lc4;
    const float* Arow1 = Arow0 + (size_t)64 * K;
    const int bn0 = n0 + lrow, bn1 = n0 + lrow + 64;
    const float* Brow0 = B + (size_t)bn0 * K + lc4;
    const float* Brow1 = B + (size_t)bn1 * K + lc4;
    const bool ok0 = bn0 < N, ok1 = bn1 < N;

    const int ntiles = K >> 4;
    float4 a0, a1, b0, b1;
    a0 = *(const float4*)(Arow0);
    a1 = *(const float4*)(Arow1);
    b0 = ok0 ? *(const float4*)(Brow0) : make_float4(0.f, 0.f, 0.f, 0.f);
    b1 = ok1 ? *(const float4*)(Brow1) : make_float4(0.f, 0.f, 0.f, 0.f);

    for (int t = 0; t < ntiles; ++t) {
        __syncthreads();
        As[lc4 + 0][lrow]      = a0.x; As[lc4 + 1][lrow]      = a0.y;
        As[lc4 + 2][lrow]      = a0.z; As[lc4 + 3][lrow]      = a0.w;
        As[lc4 + 0][lrow + 64] = a1.x; As[lc4 + 1][lrow + 64] = a1.y;
        As[lc4 + 2][lrow + 64] = a1.z; As[lc4 + 3][lrow + 64] = a1.w;
        Bs[lc4 + 0][lrow]      = b0.x; Bs[lc4 + 1][lrow]      = b0.y;
        Bs[lc4 + 2][lrow]      = b0.z; Bs[lc4 + 3][lrow]      = b0.w;
        Bs[lc4 + 0][lrow + 64] = b1.x; Bs[lc4 + 1][lrow + 64] = b1.y;
        Bs[lc4 + 2][lrow + 64] = b1.z; Bs[lc4 + 3][lrow + 64] = b1.w;
        __syncthreads();

        if (t + 1 < ntiles) {
            const int off = (t + 1) << 4;
            a0 = *(const float4*)(Arow0 + off);
            a1 = *(const float4*)(Arow1 + off);
            b0 = ok0 ? *(const float4*)(Brow0 + off) : make_float4(0.f, 0.f, 0.f, 0.f);
            b1 = ok1 ? *(const float4*)(Brow1 + off) : make_float4(0.f, 0.f, 0.f, 0.f);
        }

#pragma unroll
        for (int kk = 0; kk < 16; ++kk) {
            float4 av0 = *(const float4*)&As[kk][ty * 8];
            float4 av1 = *(const float4*)&As[kk][ty * 8 + 4];
            float4 bv0 = *(const float4*)&Bs[kk][tx * 8];
            float4 bv1 = *(const float4*)&Bs[kk][tx * 8 + 4];
            float ar[8] = {av0.x, av0.y, av0.z, av0.w, av1.x, av1.y, av1.z, av1.w};
            float br[8] = {bv0.x, bv0.y, bv0.z, bv0.w, bv1.x, bv1.y, bv1.z, bv1.w};
#pragma unroll
            for (int i = 0; i < 8; ++i)
#pragma unroll
                for (int j = 0; j < 8; ++j)
                    acc[i][j] = fmaf(ar[i], br[j], acc[i][j]);
        }
    }

#pragma unroll
    for (int i = 0; i < 8; ++i) {
        const int r = m0 + ty * 8 + i;
        const int cbase = n0 + tx * 8;
        float* Crow = C + (size_t)r * N + cbase;
#pragma unroll
        for (int j = 0; j < 8; ++j)
            if (cbase + j < N) Crow[j] = acc[i][j];
    }
}

// ---------------- RoPE (in place), d=64, pair (i, i+32) per thread ----------------
__global__ void rope_kernel(float* __restrict__ d, int nvec, int vecs_per_row) {
    const int idx = blockIdx.x * blockDim.x + threadIdx.x;
    if (idx >= nvec * 32) return;
    const int i = idx & 31;
    const int vec = idx >> 5;
    const int row = vec / vecs_per_row;
    const int t = row & (TSEQ - 1);
    float* base = d + (size_t)vec * 64;
    // inv_freq = 10000^(-i/32) ; compute angle in fp32 like the reference, trig in fp64
    const float invf = (float)exp2(-(double)i * (13.287712379549449 / 32.0));
    const float angf = (float)t * invf;
    double sd, cd;
    sincos((double)angf, &sd, &cd);
    const float s = (float)sd, c = (float)cd;
    const float x1 = base[i], x2 = base[i + 32];
    base[i]      = x1 * c - x2 * s;
    base[i + 32] = x2 * c + x1 * s;
}

// ---------------- flash attention, fp32, 64x64 tiles, causal ----------------
// grid: (TSEQ/64, B*H). 256 threads as 16x16; S microtile 4x4; O microtile 4x8.
__global__ __launch_bounds__(256) void attn_kernel() {
    extern __shared__ float smbuf[];
    float* sQ = smbuf;                 // [192][68] (k-major, transposed)
    float* sK = sQ + DQK * 68;         // [192][68]
    float* sV = sK + DQK * 68;         // [64][128]
    float* sS = sV + 64 * DV;          // [64][65]
    float* s_m    = sS + 64 * 65;
    float* s_l    = s_m + 64;
    float* s_al   = s_l + 64;
    float* s_part = s_al + 64;         // [256]

    const int tid = threadIdx.x;
    const int q0 = blockIdx.x * 64;
    const int b = blockIdx.y >> 4;
    const int h = blockIdx.y & 15;
    const int tx = tid & 15;           // n / col group
    const int ty = tid >> 4;           // m / row group

    // load Q tile (64 x 192) transposed into sQ
    for (int idx = tid; idx < 64 * DQK; idx += 256) {
        const int r = idx / DQK, c = idx - r * DQK;
        const int m = b * TSEQ + q0 + r;
        const float v = (c < 128) ? g_qproj[(size_t)m * DM + h * 128 + c]
                                  : g_qrot[(size_t)m * 1024 + h * 64 + (c - 128)];
        sQ[c * 68 + r] = v;
    }
    if (tid < 64) { s_m[tid] = -INFINITY; s_l[tid] = 0.f; }

    float acc[4][8];
#pragma unroll
    for (int i = 0; i < 4; ++i)
#pragma unroll
        for (int j = 0; j < 8; ++j) acc[i][j] = 0.f;

    for (int k0 = 0; k0 <= q0; k0 += 64) {
        __syncthreads();   // prev PV / leader reads done before smem overwrite
        for (int idx = tid; idx < 64 * DQK; idx += 256) {
            const int r = idx / DQK, c = idx - r * DQK;
            const int m = b * TSEQ + k0 + r;
            const float v = (c < 128) ? g_ukv[(size_t)m * 4096 + h * 256 + c]
                                      : g_krot[(size_t)m * 64 + (c - 128)];
            sK[c * 68 + r] = v;
        }
        for (int idx = tid; idx < 64 * DV; idx += 256) {
            const int r = idx >> 7, c = idx & 127;
            const int m = b * TSEQ + k0 + r;
            sV[idx] = g_ukv[(size_t)m * 4096 + h * 256 + 128 + c];
        }
        __syncthreads();

        // S = Q K^T (4x4 per thread)
        float s[4][4];
#pragma unroll
        for (int i = 0; i < 4; ++i)
#pragma unroll
            for (int j = 0; j < 4; ++j) s[i][j] = 0.f;
#pragma unroll 4
        for (int kk = 0; kk < DQK; ++kk) {
            float4 qv = *(const float4*)&sQ[kk * 68 + ty * 4];
            float4 kv = *(const float4*)&sK[kk * 68 + tx * 4];
            float qa[4] = {qv.x, qv.y, qv.z, qv.w};
            float ka[4] = {kv.x, kv.y, kv.z, kv.w};
#pragma unroll
            for (int i = 0; i < 4; ++i)
#pragma unroll
                for (int j = 0; j < 4; ++j)
                    s[i][j] = fmaf(qa[i], ka[j], s[i][j]);
        }
        // scale + causal mask -> sS
#pragma unroll
        for (int i = 0; i < 4; ++i) {
            const int qi = q0 + ty * 4 + i;
#pragma unroll
            for (int j = 0; j < 4; ++j) {
                const int ki = k0 + tx * 4 + j;
                sS[(ty * 4 + i) * 65 + tx * 4 + j] =
                    (ki <= qi) ? s[i][j] * ATT_SCALE : -INFINITY;
            }
        }
        __syncthreads();

        // row leaders: tile max -> new running max + alpha
        if (tid < 64) {
            const float mo = s_m[tid];
            float mx = mo;
            const float* row = &sS[tid * 65];
#pragma unroll 8
            for (int j = 0; j < 64; ++j) mx = fmaxf(mx, row[j]);
            s_al[tid] = __expf(mo - mx);
            s_m[tid] = mx;
        }
        __syncthreads();

        // all threads: exponentiate + partial row sums
        {
            const int r2 = tid >> 2;
            const int cs = (tid & 3) << 4;
            const float mr = s_m[r2];
            float* row = &sS[r2 * 65 + cs];
            float ps = 0.f;
#pragma unroll
            for (int j = 0; j < 16; ++j) {
                const float p = __expf(row[j] - mr);
                row[j] = p;
                ps += p;
            }
            s_part[tid] = ps;
        }
        __syncthreads();
        if (tid < 64)
            s_l[tid] = s_l[tid] * s_al[tid] +
                       s_part[tid * 4] + s_part[tid * 4 + 1] +
                       s_part[tid * 4 + 2] + s_part[tid * 4 + 3];

        // rescale O and accumulate P*V
        float al[4];
#pragma unroll
        for (int i = 0; i < 4; ++i) al[i] = s_al[ty * 4 + i];
#pragma unroll
        for (int i = 0; i < 4; ++i)
#pragma unroll
            for (int j = 0; j < 8; ++j) acc[i][j] *= al[i];

#pragma unroll 2
        for (int j2 = 0; j2 < 64; ++j2) {
            float p[4];
#pragma unroll
            for (int i = 0; i < 4; ++i) p[i] = sS[(ty * 4 + i) * 65 + j2];
            float4 va = *(const float4*)&sV[j2 * DV + tx * 8];
            float4 vb = *(const float4*)&sV[j2 * DV + tx * 8 + 4];
            float vv[8] = {va.x, va.y, va.z, va.w, vb.x, vb.y, vb.z, vb.w};
#pragma unroll
            for (int i = 0; i < 4; ++i)
#pragma unroll
                for (int j = 0; j < 8; ++j)
                    acc[i][j] = fmaf(p[i], vv[j], acc[i][j]);
        }
    }
    __syncthreads();

#pragma unroll
    for (int i = 0; i < 4; ++i) {
        const float invl = 1.0f / s_l[ty * 4 + i];
        const int m = b * TSEQ + q0 + ty * 4 + i;
        float* outp = &g_attn[(size_t)m * DM + h * 128 + tx * 8];
#pragma unroll
        for (int j = 0; j < 8; ++j) outp[j] = acc[i][j] * invl;
    }
}

// ---------------- launch ----------------
extern "C" void kernel_launch(void* const* d_in, const int* in_sizes, int n_in,
                              void* d_out, int out_size) {
    const float* x      = (const float*)d_in[0];
    const float* w_q    = (const float*)d_in[1];
    const float* w_dkv  = (const float*)d_in[2];
    const float* w_ukv  = (const float*)d_in[3];
    const float* w_o    = (const float*)d_in[4];
    const float* w_qrot = (const float*)d_in[5];
    const float* w_krot = (const float*)d_in[6];
    float* out = (float*)d_out;

    float *p_qproj, *p_qrot, *p_dkv, *p_ukv, *p_krot, *p_attn;
    cudaGetSymbolAddress((void**)&p_qproj, g_qproj);
    cudaGetSymbolAddress((void**)&p_qrot,  g_qrot);
    cudaGetSymbolAddress((void**)&p_dkv,   g_dkv);
    cudaGetSymbolAddress((void**)&p_ukv,   g_ukv);
    cudaGetSymbolAddress((void**)&p_krot,  g_krot);
    cudaGetSymbolAddress((void**)&p_attn,  g_attn);

    dim3 blk(256);
    // projections from x
    gemm_nt<<<dim3(DM / 128, BT / 128), blk>>>(x, w_q,    p_qproj, BT, DM,   DM);
    gemm_nt<<<dim3(1024 / 128, BT / 128), blk>>>(x, w_qrot, p_qrot, BT, 1024, DM);
    gemm_nt<<<dim3(1, BT / 128), blk>>>(x, w_krot, p_krot, BT, 64, DM);
    gemm_nt<<<dim3(512 / 128, BT / 128), blk>>>(x, w_dkv, p_dkv, BT, 512, DM);
    // up-projection
    gemm_nt<<<dim3(4096 / 128, BT / 128), blk>>>(p_dkv, w_ukv, p_ukv, BT, 4096, 512);
    // rope in place
    rope_kernel<<<(BT * 16 * 32 + 255) / 256, 256>>>(p_qrot, BT * 16, 16);
    rope_kernel<<<(BT * 32 + 255) / 256, 256>>>(p_krot, BT, 1);
    // attention
    const int smem = 38912 * 4;  // 155,648 B
    cudaFuncSetAttribute(attn_kernel, cudaFuncAttributeMaxDynamicSharedMemorySize, smem);
    attn_kernel<<<dim3(TSEQ / 64, 32), blk, smem>>>();
    // output projection
    gemm_nt<<<dim3(DM / 128, BT / 128), blk>>>(p_attn, w_o, out, BT, DM, DM);
}

// round 3
// speedup vs baseline: 1.0351x; 1.0351x over previous
#include <cuda_runtime.h>
#include <cuda_bf16.h>
#include <math.h>
#include <cstdint>

#define BT    4096
#define TSEQ  2048
#define DM    2048
#define DQK   192
#define DV    128
#define ATT_SCALE 0.07216878364870323f   // 1/sqrt(192)

// ---------------- fp32 scratch ----------------
__device__ float g_qproj[BT * DM];
__device__ float g_qrot [BT * 1024];
__device__ float g_dkv  [BT * 512];
__device__ float g_ukv  [BT * 4096];
__device__ float g_krot [BT * 64];
__device__ float g_attn [BT * DM];
// ---------------- bf16 split scratch ----------------
__device__ __nv_bfloat16 g_x_hi[BT*DM],     g_x_lo[BT*DM];
__device__ __nv_bfloat16 g_wq_hi[DM*DM],    g_wq_lo[DM*DM];
__device__ __nv_bfloat16 g_wqr_hi[1024*DM], g_wqr_lo[1024*DM];
__device__ __nv_bfloat16 g_wkr_hi[64*DM],   g_wkr_lo[64*DM];
__device__ __nv_bfloat16 g_wdkv_hi[512*DM], g_wdkv_lo[512*DM];
__device__ __nv_bfloat16 g_wukv_hi[4096*512], g_wukv_lo[4096*512];
__device__ __nv_bfloat16 g_wo_hi[DM*DM],    g_wo_lo[DM*DM];
__device__ __nv_bfloat16 g_dkv_hi[BT*512],  g_dkv_lo[BT*512];
__device__ __nv_bfloat16 g_at_hi[BT*DM],    g_at_lo[BT*DM];

// ---------------- PTX helpers (sm_80-class, safe on plain sm_103 target) ----------------
__device__ __forceinline__ uint32_t smem_u32(const void* p) {
    uint32_t a;
    asm("{ .reg .u64 t; cvta.to.shared.u64 t, %1; cvt.u32.u64 %0, t; }" : "=r"(a) : "l"(p));
    return a;
}
__device__ __forceinline__ void cp16(uint32_t s, const void* g) {
    asm volatile("cp.async.cg.shared.global [%0], [%1], 16;" :: "r"(s), "l"(g) : "memory");
}
__device__ __forceinline__ void cp_commit() {
    asm volatile("cp.async.commit_group;" ::: "memory");
}
__device__ __forceinline__ void ldm4(uint32_t* r, uint32_t addr) {
    asm volatile("ldmatrix.sync.aligned.m8n8.x4.shared.b16 {%0,%1,%2,%3}, [%4];"
        : "=r"(r[0]), "=r"(r[1]), "=r"(r[2]), "=r"(r[3]) : "r"(addr));
}
__device__ __forceinline__ void mma16816(float* c, const uint32_t* a, const uint32_t* b) {
    asm volatile(
        "mma.sync.aligned.m16n8k16.row.col.f32.bf16.bf16.f32 "
        "{%0,%1,%2,%3}, {%4,%5,%6,%7}, {%8,%9}, {%0,%1,%2,%3};"
        : "+f"(c[0]), "+f"(c[1]), "+f"(c[2]), "+f"(c[3])
        : "r"(a[0]), "r"(a[1]), "r"(a[2]), "r"(a[3]), "r"(b[0]), "r"(b[1]));
}

// ---------------- fp32 -> bf16 hi/lo split ----------------
__global__ void split_bf16(const float* __restrict__ in, __nv_bfloat16* __restrict__ hi,
                           __nv_bfloat16* __restrict__ lo, int n4) {
    int i = blockIdx.x * blockDim.x + threadIdx.x;
    if (i >= n4) return;
    float4 v = ((const float4*)in)[i];
    float a[4] = {v.x, v.y, v.z, v.w};
    __nv_bfloat16 h[4], l[4];
#pragma unroll
    for (int k = 0; k < 4; ++k) {
        h[k] = __float2bfloat16(a[k]);
        l[k] = __float2bfloat16(a[k] - __bfloat162float(h[k]));
    }
    ((__nv_bfloat162*)hi)[i*2]   = __halves2bfloat162(h[0], h[1]);
    ((__nv_bfloat162*)hi)[i*2+1] = __halves2bfloat162(h[2], h[3]);
    ((__nv_bfloat162*)lo)[i*2]   = __halves2bfloat162(l[0], l[1]);
    ((__nv_bfloat162*)lo)[i*2+1] = __halves2bfloat162(l[2], l[3]);
}

// ---------------- bf16x3 NT GEMM via mma.sync: C[M,N] = A*B^T (fp32-accurate) ----------------
// BM=128, BK=64, 256 threads (8 warps). 2-stage cp.async pipeline, swizzled 128B rows.
template<int BN>
__global__ __launch_bounds__(256, 1)
void gemm_mma(const __nv_bfloat16* __restrict__ Ah, const __nv_bfloat16* __restrict__ Al,
              const __nv_bfloat16* __restrict__ Bh, const __nv_bfloat16* __restrict__ Bl,
              float* __restrict__ C, int M, int N, int K)
{
    constexpr int ATILE = 128 * 128;          // bytes per A tile (128 rows x 64 bf16)
    constexpr int BTILE = BN * 128;
    constexpr int STG   = 2 * ATILE + 2 * BTILE;
    constexpr int WN = (BN == 128) ? 4 : 2;   // warps along N
    constexpr int WTM = 128 / (8 / WN);       // warp tile M (64 or 32)
    constexpr int MT = WTM / 16;              // m16 tiles per warp
    constexpr int NT = 4;                     // n8 tiles per warp (warp tile N = 32)

    extern __shared__ __align__(128) char smem[];
    const uint32_t d0 = smem_u32(smem);

    const int tid = threadIdx.x;
    const int wid = tid >> 5, lane = tid & 31;
    const int wn = wid % WN, wm = wid / WN;
    const int m0 = blockIdx.y * 128;
    const int n0 = blockIdx.x * BN;
    const int l7 = lane & 7;

    float acc[MT][NT][4];
#pragma unroll
    for (int i = 0; i < MT; ++i)
#pragma unroll
        for (int j = 0; j < NT; ++j)
#pragma unroll
            for (int q = 0; q < 4; ++q) acc[i][j][q] = 0.f;

    // per-lane ldmatrix row offsets (bytes within a tile)
    uint32_t arow[MT], brow[NT / 2];
    const int a_r = lane & 15;
    const int a_kh = lane >> 4;               // 0/1 -> k halves
    const int b_n = ((lane >> 4) << 3) + (lane & 7);
    const int b_kh = (lane >> 3) & 1;
#pragma unroll
    for (int mt = 0; mt < MT; ++mt) arow[mt] = (uint32_t)((wm * WTM + mt * 16 + a_r) * 128);
#pragma unroll
    for (int np = 0; np < NT / 2; ++np) brow[np] = (uint32_t)((wn * 32 + np * 16 + b_n) * 128);

    auto load_tile = [&](int t, int s) {
        const uint32_t d = d0 + (uint32_t)s * STG;
        const int k0 = t * 64;
#pragma unroll
        for (int j = 0; j < 4; ++j) {                       // A hi+lo: 1024 chunks
            const int c = tid + j * 256;
            const int row = c >> 3, ch = c & 7;
            const uint32_t sw = (uint32_t)(row * 128 + ((ch ^ (row & 7)) << 4));
            const size_t g = (size_t)(m0 + row) * K + k0 + ch * 8;
            cp16(d + sw, Ah + g);
            cp16(d + ATILE + sw, Al + g);
        }
#pragma unroll
        for (int j = 0; j < BN / 32; ++j) {                 // B hi+lo
            const int c = tid + j * 256;
            const int row = c >> 3, ch = c & 7;
            const uint32_t sw = (uint32_t)(row * 128 + ((ch ^ (row & 7)) << 4));
            const size_t g = (size_t)(n0 + row) * K + k0 + ch * 8;
            cp16(d + 2 * ATILE + sw, Bh + g);
            cp16(d + 2 * ATILE + BTILE + sw, Bl + g);
        }
        cp_commit();
    };

    const int T = K >> 6;
    load_tile(0, 0);
    if (T > 1) load_tile(1, 1);

    for (int t = 0; t < T; ++t) {
        const int s = t & 1;
        if (t + 1 < T) asm volatile("cp.async.wait_group 1;" ::: "memory");
        else           asm volatile("cp.async.wait_group 0;" ::: "memory");
        __syncthreads();

        const uint32_t AhS = d0 + (uint32_t)s * STG;
        const uint32_t AlS = AhS + ATILE;
        const uint32_t BhS = AhS + 2 * ATILE;
        const uint32_t BlS = BhS + BTILE;

#pragma unroll
        for (int kk = 0; kk < 4; ++kk) {
            const uint32_t aoff = (uint32_t)(((kk * 2 + a_kh) ^ l7) << 4);
            const uint32_t boff = (uint32_t)(((kk * 2 + b_kh) ^ l7) << 4);
            uint32_t ah[MT][4], al[MT][4], bh[NT / 2][4], bl[NT / 2][4];
#pragma unroll
            for (int mt = 0; mt < MT; ++mt) {
                ldm4(ah[mt], AhS + arow[mt] + aoff);
                ldm4(al[mt], AlS + arow[mt] + aoff);
            }
#pragma unroll
            for (int np = 0; np < NT / 2; ++np) {
                ldm4(bh[np], BhS + brow[np] + boff);
                ldm4(bl[np], BlS + brow[np] + boff);
            }
#pragma unroll
            for (int mt = 0; mt < MT; ++mt)
#pragma unroll
                for (int nt = 0; nt < NT; ++nt) {
                    const uint32_t* bhp = &bh[nt >> 1][(nt & 1) * 2];
                    const uint32_t* blp = &bl[nt >> 1][(nt & 1) * 2];
                    mma16816(acc[mt][nt], ah[mt], bhp);
                    mma16816(acc[mt][nt], ah[mt], blp);
                    mma16816(acc[mt][nt], al[mt], bhp);
                }
        }
        __syncthreads();
        if (t + 2 < T) load_tile(t + 2, s);
    }

    // epilogue
    const int cr = lane >> 2;
    const int cc = (lane & 3) * 2;
#pragma unroll
    for (int mt = 0; mt < MT; ++mt) {
        const int r0 = m0 + wm * WTM + mt * 16 + cr;
#pragma unroll
        for (int nt = 0; nt < NT; ++nt) {
            const int col = n0 + wn * 32 + nt * 8 + cc;
            *(float2*)(C + (size_t)r0 * N + col)       = make_float2(acc[mt][nt][0], acc[mt][nt][1]);
            *(float2*)(C + (size_t)(r0 + 8) * N + col) = make_float2(acc[mt][nt][2], acc[mt][nt][3]);
        }
    }
}

// ---------------- RoPE (in place), d=64, pair (i, i+32) per thread ----------------
__global__ void rope_kernel(float* __restrict__ d, int nvec, int vecs_per_row) {
    const int idx = blockIdx.x * blockDim.x + threadIdx.x;
    if (idx >= nvec * 32) return;
    const int i = idx & 31;
    const int vec = idx >> 5;
    const int row = vec / vecs_per_row;
    const int t = row & (TSEQ - 1);
    float* base = d + (size_t)vec * 64;
    const float invf = (float)exp2(-(double)i * (13.287712379549449 / 32.0));
    const float angf = (float)t * invf;
    double sd, cd;
    sincos((double)angf, &sd, &cd);
    const float s = (float)sd, c = (float)cd;
    const float x1 = base[i], x2 = base[i + 32];
    base[i]      = x1 * c - x2 * s;
    base[i + 32] = x2 * c + x1 * s;
}

// ---------------- flash attention, fp32, 64x64 tiles, causal ----------------
__global__ __launch_bounds__(256) void attn_kernel() {
    extern __shared__ float smbuf[];
    float* sQ = smbuf;                 // [192][68]
    float* sK = sQ + DQK * 68;         // [192][68]
    float* sV = sK + DQK * 68;         // [64][128]
    float* sS = sV + 64 * DV;          // [64][65]
    float* s_m    = sS + 64 * 65;
    float* s_l    = s_m + 64;
    float* s_al   = s_l + 64;
    float* s_part = s_al + 64;

    const int tid = threadIdx.x;
    const int q0 = blockIdx.x * 64;
    const int b = blockIdx.y >> 4;
    const int h = blockIdx.y & 15;
    const int tx = tid & 15;
    const int ty = tid >> 4;

    for (int idx = tid; idx < 64 * DQK; idx += 256) {
        const int r = idx / DQK, c = idx - r * DQK;
        const int m = b * TSEQ + q0 + r;
        const float v = (c < 128) ? g_qproj[(size_t)m * DM + h * 128 + c]
                                  : g_qrot[(size_t)m * 1024 + h * 64 + (c - 128)];
        sQ[c * 68 + r] = v;
    }
    if (tid < 64) { s_m[tid] = -INFINITY; s_l[tid] = 0.f; }

    float acc[4][8];
#pragma unroll
    for (int i = 0; i < 4; ++i)
#pragma unroll
        for (int j = 0; j < 8; ++j) acc[i][j] = 0.f;

    for (int k0 = 0; k0 <= q0; k0 += 64) {
        __syncthreads();
        for (int idx = tid; idx < 64 * DQK; idx += 256) {
            const int r = idx / DQK, c = idx - r * DQK;
            const int m = b * TSEQ + k0 + r;
            const float v = (c < 128) ? g_ukv[(size_t)m * 4096 + h * 256 + c]
                                      : g_krot[(size_t)m * 64 + (c - 128)];
            sK[c * 68 + r] = v;
        }
        for (int idx = tid; idx < 64 * DV; idx += 256) {
            const int r = idx >> 7, c = idx & 127;
            const int m = b * TSEQ + k0 + r;
            sV[idx] = g_ukv[(size_t)m * 4096 + h * 256 + 128 + c];
        }
        __syncthreads();

        float s[4][4];
#pragma unroll
        for (int i = 0; i < 4; ++i)
#pragma unroll
            for (int j = 0; j < 4; ++j) s[i][j] = 0.f;
#pragma unroll 4
        for (int kk = 0; kk < DQK; ++kk) {
            float4 qv = *(const float4*)&sQ[kk * 68 + ty * 4];
            float4 kv = *(const float4*)&sK[kk * 68 + tx * 4];
            float qa[4] = {qv.x, qv.y, qv.z, qv.w};
            float ka[4] = {kv.x, kv.y, kv.z, kv.w};
#pragma unroll
            for (int i = 0; i < 4; ++i)
#pragma unroll
                for (int j = 0; j < 4; ++j)
                    s[i][j] = fmaf(qa[i], ka[j], s[i][j]);
        }
#pragma unroll
        for (int i = 0; i < 4; ++i) {
            const int qi = q0 + ty * 4 + i;
#pragma unroll
            for (int j = 0; j < 4; ++j) {
                const int ki = k0 + tx * 4 + j;
                sS[(ty * 4 + i) * 65 + tx * 4 + j] =
                    (ki <= qi) ? s[i][j] * ATT_SCALE : -INFINITY;
            }
        }
        __syncthreads();

        if (tid < 64) {
            const float mo = s_m[tid];
            float mx = mo;
            const float* row = &sS[tid * 65];
#pragma unroll 8
            for (int j = 0; j < 64; ++j) mx = fmaxf(mx, row[j]);
            s_al[tid] = __expf(mo - mx);
            s_m[tid] = mx;
        }
        __syncthreads();

        {
            const int r2 = tid >> 2;
            const int cs = (tid & 3) << 4;
            const float mr = s_m[r2];
            float* row = &sS[r2 * 65 + cs];
            float ps = 0.f;
#pragma unroll
            for (int j = 0; j < 16; ++j) {
                const float p = __expf(row[j] - mr);
                row[j] = p;
                ps += p;
            }
            s_part[tid] = ps;
        }
        __syncthreads();
        if (tid < 64)
            s_l[tid] = s_l[tid] * s_al[tid] +
                       s_part[tid * 4] + s_part[tid * 4 + 1] +
                       s_part[tid * 4 + 2] + s_part[tid * 4 + 3];

        float al[4];
#pragma unroll
        for (int i = 0; i < 4; ++i) al[i] = s_al[ty * 4 + i];
#pragma unroll
        for (int i = 0; i < 4; ++i)
#pragma unroll
            for (int j = 0; j < 8; ++j) acc[i][j] *= al[i];

#pragma unroll 2
        for (int j2 = 0; j2 < 64; ++j2) {
            float p[4];
#pragma unroll
            for (int i = 0; i < 4; ++i) p[i] = sS[(ty * 4 + i) * 65 + j2];
            float4 va = *(const float4*)&sV[j2 * DV + tx * 8];
            float4 vb = *(const float4*)&sV[j2 * DV + tx * 8 + 4];
            float vv[8] = {va.x, va.y, va.z, va.w, vb.x, vb.y, vb.z, vb.w};
#pragma unroll
            for (int i = 0; i < 4; ++i)
#pragma unroll
                for (int j = 0; j < 8; ++j)
                    acc[i][j] = fmaf(p[i], vv[j], acc[i][j]);
        }
    }
    __syncthreads();

#pragma unroll
    for (int i = 0; i < 4; ++i) {
        const float invl = 1.0f / s_l[ty * 4 + i];
        const int m = b * TSEQ + q0 + ty * 4 + i;
        float* outp = &g_attn[(size_t)m * DM + h * 128 + tx * 8];
#pragma unroll
        for (int j = 0; j < 8; ++j) outp[j] = acc[i][j] * invl;
    }
}

// ---------------- host-side helpers ----------------
static void run_split(const float* src, __nv_bfloat16* hi, __nv_bfloat16* lo, size_t n) {
    int n4 = (int)(n / 4);
    split_bf16<<<(n4 + 255) / 256, 256>>>(src, hi, lo, n4);
}

template<int BN>
static void run_gemm(const __nv_bfloat16* ah, const __nv_bfloat16* al,
                     const __nv_bfloat16* bh, const __nv_bfloat16* bl,
                     float* c, int M, int N, int K) {
    constexpr int SMEM = 2 * (2 * 128 * 128 + 2 * BN * 128);
    cudaFuncSetAttribute(gemm_mma<BN>, cudaFuncAttributeMaxDynamicSharedMemorySize, SMEM);
    gemm_mma<BN><<<dim3(N / BN, M / 128), 256, SMEM>>>(ah, al, bh, bl, c, M, N, K);
}

extern "C" void kernel_launch(void* const* d_in, const int* in_sizes, int n_in,
                              void* d_out, int out_size) {
    const float* x      = (const float*)d_in[0];
    const float* w_q    = (const float*)d_in[1];
    const float* w_dkv  = (const float*)d_in[2];
    const float* w_ukv  = (const float*)d_in[3];
    const float* w_o    = (const float*)d_in[4];
    const float* w_qrot = (const float*)d_in[5];
    const float* w_krot = (const float*)d_in[6];
    float* out = (float*)d_out;

    float *p_qproj, *p_qrot, *p_dkv, *p_ukv, *p_krot, *p_attn;
    cudaGetSymbolAddress((void**)&p_qproj, g_qproj);
    cudaGetSymbolAddress((void**)&p_qrot,  g_qrot);
    cudaGetSymbolAddress((void**)&p_dkv,   g_dkv);
    cudaGetSymbolAddress((void**)&p_ukv,   g_ukv);
    cudaGetSymbolAddress((void**)&p_krot,  g_krot);
    cudaGetSymbolAddress((void**)&p_attn,  g_attn);

    __nv_bfloat16 *xh,*xl,*wqh,*wql,*wqrh,*wqrl,*wkrh,*wkrl,*wdh,*wdl,*wuh,*wul,*woh,*wol,*dh,*dl,*ath,*atl;
    cudaGetSymbolAddress((void**)&xh,  g_x_hi);   cudaGetSymbolAddress((void**)&xl,  g_x_lo);
    cudaGetSymbolAddress((void**)&wqh, g_wq_hi);  cudaGetSymbolAddress((void**)&wql, g_wq_lo);
    cudaGetSymbolAddress((void**)&wqrh,g_wqr_hi); cudaGetSymbolAddress((void**)&wqrl,g_wqr_lo);
    cudaGetSymbolAddress((void**)&wkrh,g_wkr_hi); cudaGetSymbolAddress((void**)&wkrl,g_wkr_lo);
    cudaGetSymbolAddress((void**)&wdh, g_wdkv_hi);cudaGetSymbolAddress((void**)&wdl, g_wdkv_lo);
    cudaGetSymbolAddress((void**)&wuh, g_wukv_hi);cudaGetSymbolAddress((void**)&wul, g_wukv_lo);
    cudaGetSymbolAddress((void**)&woh, g_wo_hi);  cudaGetSymbolAddress((void**)&wol, g_wo_lo);
    cudaGetSymbolAddress((void**)&dh,  g_dkv_hi); cudaGetSymbolAddress((void**)&dl,  g_dkv_lo);
    cudaGetSymbolAddress((void**)&ath, g_at_hi);  cudaGetSymbolAddress((void**)&atl, g_at_lo);

    // split inputs / weights into bf16 hi+lo
    run_split(x,      xh,  xl,  (size_t)BT * DM);
    run_split(w_q,    wqh, wql, (size_t)DM * DM);
    run_split(w_qrot, wqrh,wqrl,(size_t)1024 * DM);
    run_split(w_krot, wkrh,wkrl,(size_t)64 * DM);
    run_split(w_dkv,  wdh, wdl, (size_t)512 * DM);
    run_split(w_ukv,  wuh, wul, (size_t)4096 * 512);
    run_split(w_o,    woh, wol, (size_t)DM * DM);

    // projections (HMMA bf16x3)
    run_gemm<128>(xh, xl, wqh,  wql,  p_qproj, BT, DM,   DM);
    run_gemm<128>(xh, xl, wqrh, wqrl, p_qrot,  BT, 1024, DM);
    run_gemm<64> (xh, xl, wkrh, wkrl, p_krot,  BT, 64,   DM);
    run_gemm<128>(xh, xl, wdh,  wdl,  p_dkv,   BT, 512,  DM);
    run_split(p_dkv, dh, dl, (size_t)BT * 512);
    run_gemm<128>(dh, dl, wuh, wul, p_ukv, BT, 4096, 512);

    // rope in place
    rope_kernel<<<(BT * 16 * 32 + 255) / 256, 256>>>(p_qrot, BT * 16, 16);
    rope_kernel<<<(BT * 32 + 255) / 256, 256>>>(p_krot, BT, 1);

    // attention (fp32)
    const int smem = 38912 * 4;
    cudaFuncSetAttribute(attn_kernel, cudaFuncAttributeMaxDynamicSharedMemorySize, smem);
    attn_kernel<<<dim3(TSEQ / 64, 32), 256, smem>>>();

    // output projection
    run_split(p_attn, ath, atl, (size_t)BT * DM);
    run_gemm<128>(ath, atl, woh, wol, out, BT, DM, DM);
}

// round 4
// speedup vs baseline: 1.6578x; 1.6015x over previous
#include <cuda_runtime.h>
#include <cuda_fp16.h>
#include <math.h>
#include <cstdint>

#define BT    4096
#define TSEQ  2048
#define DM    2048
#define DQK   192
#define DV    128
#define ATT_SCALE 0.07216878364870323f   // 1/sqrt(192)

// ---------------- fp32 scratch ----------------
__device__ float g_qproj[BT * DM];
__device__ float g_qrot [BT * 1024];
__device__ float g_dkv  [BT * 512];
__device__ float g_ukv  [BT * 4096];
__device__ float g_krot [BT * 64];
__device__ float g_attn [BT * DM];
// ---------------- fp16 scratch ----------------
__device__ __half g_x_hi[BT*DM],   g_x_lo[BT*DM];
__device__ __half g_wq_h[DM*DM];
__device__ __half g_wqr_h[1024*DM];
__device__ __half g_wkr_h[64*DM];
__device__ __half g_wdkv_h[512*DM];
__device__ __half g_wukv_h[4096*512];
__device__ __half g_wo_h[DM*DM];
__device__ __half g_dkv_hi[BT*512], g_dkv_lo[BT*512];
__device__ __half g_at_hi[BT*DM],   g_at_lo[BT*DM];

// ---------------- PTX helpers (sm_80-class, safe on plain sm_103 target) ----------------
__device__ __forceinline__ void cp16(uint32_t s, const void* g) {
    asm volatile("cp.async.cg.shared.global [%0], [%1], 16;" :: "r"(s), "l"(g) : "memory");
}
__device__ __forceinline__ uint32_t smem_u32(const void* p) {
    uint32_t a;
    asm("{ .reg .u64 t; cvta.to.shared.u64 t, %1; cvt.u32.u64 %0, t; }" : "=r"(a) : "l"(p));
    return a;
}
__device__ __forceinline__ void ldm4(uint32_t* r, uint32_t addr) {
    asm volatile("ldmatrix.sync.aligned.m8n8.x4.shared.b16 {%0,%1,%2,%3}, [%4];"
        : "=r"(r[0]), "=r"(r[1]), "=r"(r[2]), "=r"(r[3]) : "r"(addr));
}
__device__ __forceinline__ void mma16816(float* c, const uint32_t* a, const uint32_t* b) {
    asm volatile(
        "mma.sync.aligned.m16n8k16.row.col.f32.f16.f16.f32 "
        "{%0,%1,%2,%3}, {%4,%5,%6,%7}, {%8,%9}, {%0,%1,%2,%3};"
        : "+f"(c[0]), "+f"(c[1]), "+f"(c[2]), "+f"(c[3])
        : "r"(a[0]), "r"(a[1]), "r"(a[2]), "r"(a[3]), "r"(b[0]), "r"(b[1]));
}

// ---------------- fp32 -> fp16 hi/lo split (activations) ----------------
__global__ void split_f16(const float* __restrict__ in, __half* __restrict__ hi,
                          __half* __restrict__ lo, int n4) {
    int i = blockIdx.x * blockDim.x + threadIdx.x;
    if (i >= n4) return;
    float4 v = ((const float4*)in)[i];
    float a[4] = {v.x, v.y, v.z, v.w};
    __half h[4], l[4];
#pragma unroll
    for (int k = 0; k < 4; ++k) {
        h[k] = __float2half_rn(a[k]);
        l[k] = __float2half_rn(a[k] - __half2float(h[k]));
    }
    ((__half2*)hi)[i*2]   = __halves2half2(h[0], h[1]);
    ((__half2*)hi)[i*2+1] = __halves2half2(h[2], h[3]);
    ((__half2*)lo)[i*2]   = __halves2half2(l[0], l[1]);
    ((__half2*)lo)[i*2+1] = __halves2half2(l[2], l[3]);
}

// ---------------- fp32 -> fp16 (weights, single) ----------------
__global__ void conv_f16(const float* __restrict__ in, __half* __restrict__ out, int n4) {
    int i = blockIdx.x * blockDim.x + threadIdx.x;
    if (i >= n4) return;
    float4 v = ((const float4*)in)[i];
    ((__half2*)out)[i*2]   = __halves2half2(__float2half_rn(v.x), __float2half_rn(v.y));
    ((__half2*)out)[i*2+1] = __halves2half2(__float2half_rn(v.z), __float2half_rn(v.w));
}

// ---------------- fp16x2 NT GEMM via mma.sync: C[M,N] = (Ah+Al)*Bh^T ----------------
// BM=128, BK=64, 256 threads (8 warps). 2-stage cp.async pipeline, swizzled 128B rows.
template<int BN>
__global__ __launch_bounds__(256, 2)
void gemm_mma(const __half* __restrict__ Ah, const __half* __restrict__ Al,
              const __half* __restrict__ Bh,
              float* __restrict__ C, int M, int N, int K)
{
    constexpr int ATILE = 128 * 128;          // bytes per A-half tile (128 rows x 64 fp16)
    constexpr int BTILE = BN * 128;
    constexpr int STG   = 2 * ATILE + BTILE;
    constexpr int WN = (BN == 128) ? 4 : 2;
    constexpr int WTM = 128 / (8 / WN);       // 64 or 32
    constexpr int MT = WTM / 16;
    constexpr int NT = 4;                     // warp tile N = 32

    extern __shared__ __align__(128) char smem[];
    const uint32_t d0 = smem_u32(smem);

    const int tid = threadIdx.x;
    const int wid = tid >> 5, lane = tid & 31;
    const int wn = wid % WN, wm = wid / WN;
    const int m0 = blockIdx.y * 128;
    const int n0 = blockIdx.x * BN;
    const int l7 = lane & 7;

    float acc[MT][NT][4];
#pragma unroll
    for (int i = 0; i < MT; ++i)
#pragma unroll
        for (int j = 0; j < NT; ++j)
#pragma unroll
            for (int q = 0; q < 4; ++q) acc[i][j][q] = 0.f;

    uint32_t arow[MT], brow[NT / 2];
    const int a_r = lane & 15;
    const int a_kh = lane >> 4;
    const int b_n = ((lane >> 4) << 3) + (lane & 7);
    const int b_kh = (lane >> 3) & 1;
#pragma unroll
    for (int mt = 0; mt < MT; ++mt) arow[mt] = (uint32_t)((wm * WTM + mt * 16 + a_r) * 128);
#pragma unroll
    for (int np = 0; np < NT / 2; ++np) brow[np] = (uint32_t)((wn * 32 + np * 16 + b_n) * 128);

    auto load_tile = [&](int t, int s) {
        const uint32_t d = d0 + (uint32_t)s * STG;
        const int k0 = t * 64;
#pragma unroll
        for (int j = 0; j < 4; ++j) {                       // A hi+lo
            const int c = tid + j * 256;
            const int row = c >> 3, ch = c & 7;
            const uint32_t sw = (uint32_t)(row * 128 + ((ch ^ (row & 7)) << 4));
            const size_t g = (size_t)(m0 + row) * K + k0 + ch * 8;
            cp16(d + sw, Ah + g);
            cp16(d + ATILE + sw, Al + g);
        }
#pragma unroll
        for (int j = 0; j < BN / 32; ++j) {                 // B hi
            const int c = tid + j * 256;
            const int row = c >> 3, ch = c & 7;
            const uint32_t sw = (uint32_t)(row * 128 + ((ch ^ (row & 7)) << 4));
            const size_t g = (size_t)(n0 + row) * K + k0 + ch * 8;
            cp16(d + 2 * ATILE + sw, Bh + g);
        }
        asm volatile("cp.async.commit_group;" ::: "memory");
    };

    const int T = K >> 6;
    load_tile(0, 0);
    if (T > 1) load_tile(1, 1);

    for (int t = 0; t < T; ++t) {
        const int s = t & 1;
        if (t + 1 < T) asm volatile("cp.async.wait_group 1;" ::: "memory");
        else           asm volatile("cp.async.wait_group 0;" ::: "memory");
        __syncthreads();

        const uint32_t AhS = d0 + (uint32_t)s * STG;
        const uint32_t AlS = AhS + ATILE;
        const uint32_t BhS = AhS + 2 * ATILE;

#pragma unroll
        for (int kk = 0; kk < 4; ++kk) {
            const uint32_t aoff = (uint32_t)(((kk * 2 + a_kh) ^ l7) << 4);
            const uint32_t boff = (uint32_t)(((kk * 2 + b_kh) ^ l7) << 4);
            uint32_t ah[MT][4], al[MT][4], bh[NT / 2][4];
#pragma unroll
            for (int mt = 0; mt < MT; ++mt) {
                ldm4(ah[mt], AhS + arow[mt] + aoff);
                ldm4(al[mt], AlS + arow[mt] + aoff);
            }
#pragma unroll
            for (int np = 0; np < NT / 2; ++np)
                ldm4(bh[np], BhS + brow[np] + boff);
#pragma unroll
            for (int mt = 0; mt < MT; ++mt)
#pragma unroll
                for (int nt = 0; nt < NT; ++nt) {
                    const uint32_t* bhp = &bh[nt >> 1][(nt & 1) * 2];
                    mma16816(acc[mt][nt], ah[mt], bhp);
                    mma16816(acc[mt][nt], al[mt], bhp);
                }
        }
        __syncthreads();
        if (t + 2 < T) load_tile(t + 2, s);
    }

    const int cr = lane >> 2;
    const int cc = (lane & 3) * 2;
#pragma unroll
    for (int mt = 0; mt < MT; ++mt) {
        const int r0 = m0 + wm * WTM + mt * 16 + cr;
#pragma unroll
        for (int nt = 0; nt < NT; ++nt) {
            const int col = n0 + wn * 32 + nt * 8 + cc;
            *(float2*)(C + (size_t)r0 * N + col)       = make_float2(acc[mt][nt][0], acc[mt][nt][1]);
            *(float2*)(C + (size_t)(r0 + 8) * N + col) = make_float2(acc[mt][nt][2], acc[mt][nt][3]);
        }
    }
}

// ---------------- RoPE (in place), d=64, pair (i, i+32) per thread ----------------
__global__ void rope_kernel(float* __restrict__ d, int nvec, int vecs_per_row) {
    const int idx = blockIdx.x * blockDim.x + threadIdx.x;
    if (idx >= nvec * 32) return;
    const int i = idx & 31;
    const int vec = idx >> 5;
    const int row = vec / vecs_per_row;
    const int t = row & (TSEQ - 1);
    float* base = d + (size_t)vec * 64;
    const float invf = (float)exp2(-(double)i * (13.287712379549449 / 32.0));
    const float angf = (float)t * invf;
    double sd, cd;
    sincos((double)angf, &sd, &cd);
    const float s = (float)sd, c = (float)cd;
    const float x1 = base[i], x2 = base[i + 32];
    base[i]      = x1 * c - x2 * s;
    base[i + 32] = x2 * c + x1 * s;
}

// ---------------- flash attention, fp32, 64x64 tiles, causal ----------------
__global__ __launch_bounds__(256) void attn_kernel() {
    extern __shared__ float smbuf[];
    float* sQ = smbuf;                 // [192][68]
    float* sK = sQ + DQK * 68;         // [192][68]
    float* sV = sK + DQK * 68;         // [64][128]
    float* sS = sV + 64 * DV;          // [64][65]
    float* s_m    = sS + 64 * 65;
    float* s_l    = s_m + 64;
    float* s_al   = s_l + 64;
    float* s_part = s_al + 64;

    const int tid = threadIdx.x;
    const int q0 = blockIdx.x * 64;
    const int b = blockIdx.y >> 4;
    const int h = blockIdx.y & 15;
    const int tx = tid & 15;
    const int ty = tid >> 4;

    for (int idx = tid; idx < 64 * DQK; idx += 256) {
        const int r = idx / DQK, c = idx - r * DQK;
        const int m = b * TSEQ + q0 + r;
        const float v = (c < 128) ? g_qproj[(size_t)m * DM + h * 128 + c]
                                  : g_qrot[(size_t)m * 1024 + h * 64 + (c - 128)];
        sQ[c * 68 + r] = v;
    }
    if (tid < 64) { s_m[tid] = -INFINITY; s_l[tid] = 0.f; }

    float acc[4][8];
#pragma unroll
    for (int i = 0; i < 4; ++i)
#pragma unroll
        for (int j = 0; j < 8; ++j) acc[i][j] = 0.f;

    for (int k0 = 0; k0 <= q0; k0 += 64) {
        __syncthreads();
        for (int idx = tid; idx < 64 * DQK; idx += 256) {
            const int r = idx / DQK, c = idx - r * DQK;
            const int m = b * TSEQ + k0 + r;
            const float v = (c < 128) ? g_ukv[(size_t)m * 4096 + h * 256 + c]
                                      : g_krot[(size_t)m * 64 + (c - 128)];
            sK[c * 68 + r] = v;
        }
        for (int idx = tid; idx < 64 * DV; idx += 256) {
            const int r = idx >> 7, c = idx & 127;
            const int m = b * TSEQ + k0 + r;
            sV[idx] = g_ukv[(size_t)m * 4096 + h * 256 + 128 + c];
        }
        __syncthreads();

        float s[4][4];
#pragma unroll
        for (int i = 0; i < 4; ++i)
#pragma unroll
            for (int j = 0; j < 4; ++j) s[i][j] = 0.f;
#pragma unroll 4
        for (int kk = 0; kk < DQK; ++kk) {
            float4 qv = *(const float4*)&sQ[kk * 68 + ty * 4];
            float4 kv = *(const float4*)&sK[kk * 68 + tx * 4];
            float qa[4] = {qv.x, qv.y, qv.z, qv.w};
            float ka[4] = {kv.x, kv.y, kv.z, kv.w};
#pragma unroll
            for (int i = 0; i < 4; ++i)
#pragma unroll
                for (int j = 0; j < 4; ++j)
                    s[i][j] = fmaf(qa[i], ka[j], s[i][j]);
        }
#pragma unroll
        for (int i = 0; i < 4; ++i) {
            const int qi = q0 + ty * 4 + i;
#pragma unroll
            for (int j = 0; j < 4; ++j) {
                const int ki = k0 + tx * 4 + j;
                sS[(ty * 4 + i) * 65 + tx * 4 + j] =
                    (ki <= qi) ? s[i][j] * ATT_SCALE : -INFINITY;
            }
        }
        __syncthreads();

        if (tid < 64) {
            const float mo = s_m[tid];
            float mx = mo;
            const float* row = &sS[tid * 65];
#pragma unroll 8
            for (int j = 0; j < 64; ++j) mx = fmaxf(mx, row[j]);
            s_al[tid] = __expf(mo - mx);
            s_m[tid] = mx;
        }
        __syncthreads();

        {
            const int r2 = tid >> 2;
            const int cs = (tid & 3) << 4;
            const float mr = s_m[r2];
            float* row = &sS[r2 * 65 + cs];
            float ps = 0.f;
#pragma unroll
            for (int j = 0; j < 16; ++j) {
                const float p = __expf(row[j] - mr);
                row[j] = p;
                ps += p;
            }
            s_part[tid] = ps;
        }
        __syncthreads();
        if (tid < 64)
            s_l[tid] = s_l[tid] * s_al[tid] +
                       s_part[tid * 4] + s_part[tid * 4 + 1] +
                       s_part[tid * 4 + 2] + s_part[tid * 4 + 3];

        float al[4];
#pragma unroll
        for (int i = 0; i < 4; ++i) al[i] = s_al[ty * 4 + i];
#pragma unroll
        for (int i = 0; i < 4; ++i)
#pragma unroll
            for (int j = 0; j < 8; ++j) acc[i][j] *= al[i];

#pragma unroll 2
        for (int j2 = 0; j2 < 64; ++j2) {
            float p[4];
#pragma unroll
            for (int i = 0; i < 4; ++i) p[i] = sS[(ty * 4 + i) * 65 + j2];
            float4 va = *(const float4*)&sV[j2 * DV + tx * 8];
            float4 vb = *(const float4*)&sV[j2 * DV + tx * 8 + 4];
            float vv[8] = {va.x, va.y, va.z, va.w, vb.x, vb.y, vb.z, vb.w};
#pragma unroll
            for (int i = 0; i < 4; ++i)
#pragma unroll
                for (int j = 0; j < 8; ++j)
                    acc[i][j] = fmaf(p[i], vv[j], acc[i][j]);
        }
    }
    __syncthreads();

#pragma unroll
    for (int i = 0; i < 4; ++i) {
        const float invl = 1.0f / s_l[ty * 4 + i];
        const int m = b * TSEQ + q0 + ty * 4 + i;
        float* outp = &g_attn[(size_t)m * DM + h * 128 + tx * 8];
#pragma unroll
        for (int j = 0; j < 8; ++j) outp[j] = acc[i][j] * invl;
    }
}

// ---------------- host-side helpers ----------------
static void run_split(const float* src, __half* hi, __half* lo, size_t n) {
    int n4 = (int)(n / 4);
    split_f16<<<(n4 + 255) / 256, 256>>>(src, hi, lo, n4);
}
static void run_conv(const float* src, __half* dst, size_t n) {
    int n4 = (int)(n / 4);
    conv_f16<<<(n4 + 255) / 256, 256>>>(src, dst, n4);
}
template<int BN>
static void run_gemm(const __half* ah, const __half* al, const __half* bh,
                     float* c, int M, int N, int K) {
    constexpr int SMEM = 2 * (2 * 128 * 128 + BN * 128);
    cudaFuncSetAttribute(gemm_mma<BN>, cudaFuncAttributeMaxDynamicSharedMemorySize, SMEM);
    gemm_mma<BN><<<dim3(N / BN, M / 128), 256, SMEM>>>(ah, al, bh, c, M, N, K);
}

extern "C" void kernel_launch(void* const* d_in, const int* in_sizes, int n_in,
                              void* d_out, int out_size) {
    const float* x      = (const float*)d_in[0];
    const float* w_q    = (const float*)d_in[1];
    const float* w_dkv  = (const float*)d_in[2];
    const float* w_ukv  = (const float*)d_in[3];
    const float* w_o    = (const float*)d_in[4];
    const float* w_qrot = (const float*)d_in[5];
    const float* w_krot = (const float*)d_in[6];
    float* out = (float*)d_out;

    float *p_qproj, *p_qrot, *p_dkv, *p_ukv, *p_krot, *p_attn;
    cudaGetSymbolAddress((void**)&p_qproj, g_qproj);
    cudaGetSymbolAddress((void**)&p_qrot,  g_qrot);
    cudaGetSymbolAddress((void**)&p_dkv,   g_dkv);
    cudaGetSymbolAddress((void**)&p_ukv,   g_ukv);
    cudaGetSymbolAddress((void**)&p_krot,  g_krot);
    cudaGetSymbolAddress((void**)&p_attn,  g_attn);

    __half *xh,*xl,*wqh,*wqrh,*wkrh,*wdh,*wuh,*woh,*dh,*dl,*ath,*atl;
    cudaGetSymbolAddress((void**)&xh,  g_x_hi);   cudaGetSymbolAddress((void**)&xl,  g_x_lo);
    cudaGetSymbolAddress((void**)&wqh, g_wq_h);
    cudaGetSymbolAddress((void**)&wqrh,g_wqr_h);
    cudaGetSymbolAddress((void**)&wkrh,g_wkr_h);
    cudaGetSymbolAddress((void**)&wdh, g_wdkv_h);
    cudaGetSymbolAddress((void**)&wuh, g_wukv_h);
    cudaGetSymbolAddress((void**)&woh, g_wo_h);
    cudaGetSymbolAddress((void**)&dh,  g_dkv_hi); cudaGetSymbolAddress((void**)&dl,  g_dkv_lo);
    cudaGetSymbolAddress((void**)&ath, g_at_hi);  cudaGetSymbolAddress((void**)&atl, g_at_lo);

    // launch order arranged so 0-based launch #3 = the big w_q GEMM (ncu captures idx 3)
    run_split(x, xh, xl, (size_t)BT * DM);                 // 0
    run_conv(w_q,    wqh,  (size_t)DM * DM);               // 1
    run_conv(w_qrot, wqrh, (size_t)1024 * DM);             // 2
    run_gemm<128>(xh, xl, wqh, p_qproj, BT, DM, DM);       // 3  <- profiled
    run_conv(w_krot, wkrh, (size_t)64 * DM);               // 4
    run_conv(w_dkv,  wdh,  (size_t)512 * DM);              // 5
    run_conv(w_ukv,  wuh,  (size_t)4096 * 512);            // 6
    run_conv(w_o,    woh,  (size_t)DM * DM);               // 7
    run_gemm<128>(xh, xl, wqrh, p_qrot, BT, 1024, DM);     // 8
    run_gemm<64> (xh, xl, wkrh, p_krot, BT, 64,   DM);     // 9
    run_gemm<128>(xh, xl, wdh,  p_dkv,  BT, 512,  DM);     // 10
    run_split(p_dkv, dh, dl, (size_t)BT * 512);            // 11
    run_gemm<128>(dh, dl, wuh, p_ukv, BT, 4096, 512);      // 12

    rope_kernel<<<(BT * 16 * 32 + 255) / 256, 256>>>(p_qrot, BT * 16, 16);  // 13
    rope_kernel<<<(BT * 32 + 255) / 256, 256>>>(p_krot, BT, 1);             // 14

    const int smem = 38912 * 4;
    cudaFuncSetAttribute(attn_kernel, cudaFuncAttributeMaxDynamicSharedMemorySize, smem);
    attn_kernel<<<dim3(TSEQ / 64, 32), 256, smem>>>();     // 15

    run_split(p_attn, ath, atl, (size_t)BT * DM);          // 16
    run_gemm<128>(ath, atl, woh, out, BT, DM, DM);         // 17
}

// round 5
// speedup vs baseline: 4.7625x; 2.8729x over previous
#include <cuda_runtime.h>
#include <cuda_fp16.h>
#include <math.h>
#include <cstdint>

#define BT    4096
#define TSEQ  2048
#define DM    2048
#define DQK   192
#define DV    128
#define ATT_SCALE 0.07216878364870323f   // 1/sqrt(192)
#define NEG_BIG  -1e30f

// ---------------- fp32 scratch ----------------
__device__ float g_qproj[BT * DM];
__device__ float g_qrot [BT * 1024];
__device__ float g_dkv  [BT * 512];
__device__ float g_ukv  [BT * 4096];
__device__ float g_krot [BT * 64];
__device__ float g_attn [BT * DM];
// ---------------- fp16 gemm operands ----------------
__device__ __half g_x_hi[BT*DM],   g_x_lo[BT*DM];
__device__ __half g_wq_h[DM*DM];
__device__ __half g_wqr_h[1024*DM];
__device__ __half g_wkr_h[64*DM];
__device__ __half g_wdkv_h[512*DM];
__device__ __half g_wukv_h[4096*512];
__device__ __half g_wo_h[DM*DM];
__device__ __half g_dkv_hi[BT*512], g_dkv_lo[BT*512];
__device__ __half g_at_hi[BT*DM],   g_at_lo[BT*DM];
// ---------------- fp16 attention operands (packed per (b,h)) ----------------
__device__ __half g_qh[32*TSEQ*DQK], g_ql[32*TSEQ*DQK];   // [bh][t][192], SCALE folded
__device__ __half g_kh[32*TSEQ*DQK], g_kl[32*TSEQ*DQK];   // [bh][t][192]
__device__ __half g_vh[32*DV*TSEQ],  g_vl[32*DV*TSEQ];    // [bh][dv][t] (transposed)

// ---------------- PTX helpers ----------------
__device__ __forceinline__ void cp16(uint32_t s, const void* g) {
    asm volatile("cp.async.cg.shared.global [%0], [%1], 16;" :: "r"(s), "l"(g) : "memory");
}
__device__ __forceinline__ uint32_t smem_u32(const void* p) {
    uint32_t a;
    asm("{ .reg .u64 t; cvta.to.shared.u64 t, %1; cvt.u32.u64 %0, t; }" : "=r"(a) : "l"(p));
    return a;
}
__device__ __forceinline__ void ldm4(uint32_t* r, uint32_t addr) {
    asm volatile("ldmatrix.sync.aligned.m8n8.x4.shared.b16 {%0,%1,%2,%3}, [%4];"
        : "=r"(r[0]), "=r"(r[1]), "=r"(r[2]), "=r"(r[3]) : "r"(addr));
}
__device__ __forceinline__ void mma16816(float* c, const uint32_t* a, const uint32_t* b) {
    asm volatile(
        "mma.sync.aligned.m16n8k16.row.col.f32.f16.f16.f32 "
        "{%0,%1,%2,%3}, {%4,%5,%6,%7}, {%8,%9}, {%0,%1,%2,%3};"
        : "+f"(c[0]), "+f"(c[1]), "+f"(c[2]), "+f"(c[3])
        : "r"(a[0]), "r"(a[1]), "r"(a[2]), "r"(a[3]), "r"(b[0]), "r"(b[1]));
}

// ---------------- fp32 -> fp16 hi/lo split / convert ----------------
__global__ void split_f16(const float* __restrict__ in, __half* __restrict__ hi,
                          __half* __restrict__ lo, int n4) {
    int i = blockIdx.x * blockDim.x + threadIdx.x;
    if (i >= n4) return;
    float4 v = ((const float4*)in)[i];
    float a[4] = {v.x, v.y, v.z, v.w};
    __half h[4], l[4];
#pragma unroll
    for (int k = 0; k < 4; ++k) {
        h[k] = __float2half_rn(a[k]);
        l[k] = __float2half_rn(a[k] - __half2float(h[k]));
    }
    ((__half2*)hi)[i*2]   = __halves2half2(h[0], h[1]);
    ((__half2*)hi)[i*2+1] = __halves2half2(h[2], h[3]);
    ((__half2*)lo)[i*2]   = __halves2half2(l[0], l[1]);
    ((__half2*)lo)[i*2+1] = __halves2half2(l[2], l[3]);
}
__global__ void conv_f16(const float* __restrict__ in, __half* __restrict__ out, int n4) {
    int i = blockIdx.x * blockDim.x + threadIdx.x;
    if (i >= n4) return;
    float4 v = ((const float4*)in)[i];
    ((__half2*)out)[i*2]   = __halves2half2(__float2half_rn(v.x), __float2half_rn(v.y));
    ((__half2*)out)[i*2+1] = __halves2half2(__float2half_rn(v.z), __float2half_rn(v.w));
}

// ---------------- fp16x2 NT GEMM via mma.sync (unchanged from R4) ----------------
template<int BN>
__global__ __launch_bounds__(256, 2)
void gemm_mma(const __half* __restrict__ Ah, const __half* __restrict__ Al,
              const __half* __restrict__ Bh,
              float* __restrict__ C, int M, int N, int K)
{
    constexpr int ATILE = 128 * 128;
    constexpr int BTILE = BN * 128;
    constexpr int STG   = 2 * ATILE + BTILE;
    constexpr int WN = (BN == 128) ? 4 : 2;
    constexpr int WTM = 128 / (8 / WN);
    constexpr int MT = WTM / 16;
    constexpr int NT = 4;

    extern __shared__ __align__(128) char smem[];
    const uint32_t d0 = smem_u32(smem);

    const int tid = threadIdx.x;
    const int wid = tid >> 5, lane = tid & 31;
    const int wn = wid % WN, wm = wid / WN;
    const int m0 = blockIdx.y * 128;
    const int n0 = blockIdx.x * BN;
    const int l7 = lane & 7;

    float acc[MT][NT][4];
#pragma unroll
    for (int i = 0; i < MT; ++i)
#pragma unroll
        for (int j = 0; j < NT; ++j)
#pragma unroll
            for (int q = 0; q < 4; ++q) acc[i][j][q] = 0.f;

    uint32_t arow[MT], brow[NT / 2];
    const int a_r = lane & 15;
    const int a_kh = lane >> 4;
    const int b_n = ((lane >> 4) << 3) + (lane & 7);
    const int b_kh = (lane >> 3) & 1;
#pragma unroll
    for (int mt = 0; mt < MT; ++mt) arow[mt] = (uint32_t)((wm * WTM + mt * 16 + a_r) * 128);
#pragma unroll
    for (int np = 0; np < NT / 2; ++np) brow[np] = (uint32_t)((wn * 32 + np * 16 + b_n) * 128);

    auto load_tile = [&](int t, int s) {
        const uint32_t d = d0 + (uint32_t)s * STG;
        const int k0 = t * 64;
#pragma unroll
        for (int j = 0; j < 4; ++j) {
            const int c = tid + j * 256;
            const int row = c >> 3, ch = c & 7;
            const uint32_t sw = (uint32_t)(row * 128 + ((ch ^ (row & 7)) << 4));
            const size_t g = (size_t)(m0 + row) * K + k0 + ch * 8;
            cp16(d + sw, Ah + g);
            cp16(d + ATILE + sw, Al + g);
        }
#pragma unroll
        for (int j = 0; j < BN / 32; ++j) {
            const int c = tid + j * 256;
            const int row = c >> 3, ch = c & 7;
            const uint32_t sw = (uint32_t)(row * 128 + ((ch ^ (row & 7)) << 4));
            const size_t g = (size_t)(n0 + row) * K + k0 + ch * 8;
            cp16(d + 2 * ATILE + sw, Bh + g);
        }
        asm volatile("cp.async.commit_group;" ::: "memory");
    };

    const int T = K >> 6;
    load_tile(0, 0);
    if (T > 1) load_tile(1, 1);

    for (int t = 0; t < T; ++t) {
        const int s = t & 1;
        if (t + 1 < T) asm volatile("cp.async.wait_group 1;" ::: "memory");
        else           asm volatile("cp.async.wait_group 0;" ::: "memory");
        __syncthreads();

        const uint32_t AhS = d0 + (uint32_t)s * STG;
        const uint32_t AlS = AhS + ATILE;
        const uint32_t BhS = AhS + 2 * ATILE;

#pragma unroll
        for (int kk = 0; kk < 4; ++kk) {
            const uint32_t aoff = (uint32_t)(((kk * 2 + a_kh) ^ l7) << 4);
            const uint32_t boff = (uint32_t)(((kk * 2 + b_kh) ^ l7) << 4);
            uint32_t ah[MT][4], al[MT][4], bh[NT / 2][4];
#pragma unroll
            for (int mt = 0; mt < MT; ++mt) {
                ldm4(ah[mt], AhS + arow[mt] + aoff);
                ldm4(al[mt], AlS + arow[mt] + aoff);
            }
#pragma unroll
            for (int np = 0; np < NT / 2; ++np)
                ldm4(bh[np], BhS + brow[np] + boff);
#pragma unroll
            for (int mt = 0; mt < MT; ++mt)
#pragma unroll
                for (int nt = 0; nt < NT; ++nt) {
                    const uint32_t* bhp = &bh[nt >> 1][(nt & 1) * 2];
                    mma16816(acc[mt][nt], ah[mt], bhp);
                    mma16816(acc[mt][nt], al[mt], bhp);
                }
        }
        __syncthreads();
        if (t + 2 < T) load_tile(t + 2, s);
    }

    const int cr = lane >> 2;
    const int cc = (lane & 3) * 2;
#pragma unroll
    for (int mt = 0; mt < MT; ++mt) {
        const int r0 = m0 + wm * WTM + mt * 16 + cr;
#pragma unroll
        for (int nt = 0; nt < NT; ++nt) {
            const int col = n0 + wn * 32 + nt * 8 + cc;
            *(float2*)(C + (size_t)r0 * N + col)       = make_float2(acc[mt][nt][0], acc[mt][nt][1]);
            *(float2*)(C + (size_t)(r0 + 8) * N + col) = make_float2(acc[mt][nt][2], acc[mt][nt][3]);
        }
    }
}

// ---------------- RoPE (in place) ----------------
__global__ void rope_kernel(float* __restrict__ d, int nvec, int vecs_per_row) {
    const int idx = blockIdx.x * blockDim.x + threadIdx.x;
    if (idx >= nvec * 32) return;
    const int i = idx & 31;
    const int vec = idx >> 5;
    const int row = vec / vecs_per_row;
    const int t = row & (TSEQ - 1);
    float* base = d + (size_t)vec * 64;
    const float invf = (float)exp2(-(double)i * (13.287712379549449 / 32.0));
    const float angf = (float)t * invf;
    double sd, cd;
    sincos((double)angf, &sd, &cd);
    const float s = (float)sd, c = (float)cd;
    const float x1 = base[i], x2 = base[i + 32];
    base[i]      = x1 * c - x2 * s;
    base[i + 32] = x2 * c + x1 * s;
}

// ---------------- pack helpers ----------------
__device__ __forceinline__ void split8_store(const float* v, __half* oh, __half* ol, size_t off) {
    uint4 uh, ul;
    uint32_t* ph = (uint32_t*)&uh;
    uint32_t* pl = (uint32_t*)&ul;
#pragma unroll
    for (int q = 0; q < 4; ++q) {
        float2 f = make_float2(v[2*q], v[2*q+1]);
        __half2 h = __float22half2_rn(f);
        float2 r = make_float2(f.x - __low2float(h), f.y - __high2float(h));
        __half2 l = __float22half2_rn(r);
        ph[q] = *(uint32_t*)&h;
        pl[q] = *(uint32_t*)&l;
    }
    *(uint4*)(oh + off) = uh;
    *(uint4*)(ol + off) = ul;
}

// q: gather qproj/qrot (roped), fold SCALE, split hi/lo -> [bh][t][192]
__global__ void pack_q(const float* __restrict__ qp, const float* __restrict__ qr,
                       __half* __restrict__ oh, __half* __restrict__ ol) {
    int i = blockIdx.x * blockDim.x + threadIdx.x;   // < 32*2048*24
    int c8 = i % 24;
    int mt = i / 24;
    int bh = mt >> 11, t = mt & 2047;
    int b = bh >> 4, h = bh & 15;
    size_t m = (size_t)b * TSEQ + t;
    float v[8];
    if (c8 < 16) {
        const float4* p = (const float4*)(qp + m * DM + h * 128 + c8 * 8);
        float4 a = p[0], bq = p[1];
        v[0]=a.x; v[1]=a.y; v[2]=a.z; v[3]=a.w; v[4]=bq.x; v[5]=bq.y; v[6]=bq.z; v[7]=bq.w;
    } else {
        const float4* p = (const float4*)(qr + m * 1024 + h * 64 + (c8 - 16) * 8);
        float4 a = p[0], bq = p[1];
        v[0]=a.x; v[1]=a.y; v[2]=a.z; v[3]=a.w; v[4]=bq.x; v[5]=bq.y; v[6]=bq.z; v[7]=bq.w;
    }
#pragma unroll
    for (int q = 0; q < 8; ++q) v[q] *= ATT_SCALE;
    split8_store(v, oh, ol, ((size_t)bh * TSEQ + t) * DQK + c8 * 8);
}

// k: gather ukv/krot (roped), split hi/lo -> [bh][t][192]
__global__ void pack_k(const float* __restrict__ ukv, const float* __restrict__ kr,
                       __half* __restrict__ oh, __half* __restrict__ ol) {
    int i = blockIdx.x * blockDim.x + threadIdx.x;
    int c8 = i % 24;
    int mt = i / 24;
    int bh = mt >> 11, t = mt & 2047;
    int b = bh >> 4, h = bh & 15;
    size_t m = (size_t)b * TSEQ + t;
    float v[8];
    if (c8 < 16) {
        const float4* p = (const float4*)(ukv + m * 4096 + h * 256 + c8 * 8);
        float4 a = p[0], bq = p[1];
        v[0]=a.x; v[1]=a.y; v[2]=a.z; v[3]=a.w; v[4]=bq.x; v[5]=bq.y; v[6]=bq.z; v[7]=bq.w;
    } else {
        const float4* p = (const float4*)(kr + m * 64 + (c8 - 16) * 8);
        float4 a = p[0], bq = p[1];
        v[0]=a.x; v[1]=a.y; v[2]=a.z; v[3]=a.w; v[4]=bq.x; v[5]=bq.y; v[6]=bq.z; v[7]=bq.w;
    }
    split8_store(v, oh, ol, ((size_t)bh * TSEQ + t) * DQK + c8 * 8);
}

// v: transpose [t][dv] -> [bh][dv][t], split hi/lo
__global__ void pack_vt(const float* __restrict__ ukv,
                        __half* __restrict__ oh, __half* __restrict__ ol) {
    __shared__ float tile[32][33];
    int t0 = blockIdx.x * 32, c0 = blockIdx.y * 32, bh = blockIdx.z;
    int b = bh >> 4, h = bh & 15;
    int tx = threadIdx.x, ty = threadIdx.y;   // 32 x 8
#pragma unroll
    for (int j = 0; j < 4; ++j) {
        int t = t0 + ty + j * 8;
        tile[ty + j * 8][tx] = ukv[((size_t)b * TSEQ + t) * 4096 + h * 256 + 128 + c0 + tx];
    }
    __syncthreads();
#pragma unroll
    for (int j = 0; j < 4; ++j) {
        int c = c0 + ty + j * 8;
        float x = tile[tx][ty + j * 8];
        __half hh = __float2half_rn(x);
        __half lh = __float2half_rn(x - __half2float(hh));
        size_t off = ((size_t)bh * DV + c) * TSEQ + t0 + tx;
        oh[off] = hh;
        ol[off] = lh;
    }
}

// ---------------- tensor-core flash attention ----------------
// BQ=128, BK=64, 8 warps. Q in smem (hi/lo), K double-buffered, V single.
#define QPL  49152           // 128 rows x 384B
#define KPL  24576           // 64 x 384B
#define KSTG (2*KPL)
#define VPL  16384           // 128 x 128B
#define ATT_SMEM (2*QPL + 2*KSTG + 2*VPL)   // 229376

__global__ __launch_bounds__(256, 1) void attn_mma(
    const __half* __restrict__ qh, const __half* __restrict__ ql,
    const __half* __restrict__ kh, const __half* __restrict__ kl,
    const __half* __restrict__ vh, const __half* __restrict__ vl)
{
    extern __shared__ __align__(128) char smem[];
    const uint32_t S0 = smem_u32(smem);
    const int tid = threadIdx.x, wid = tid >> 5, lane = tid & 31;
    const int qt = gridDim.x - 1 - blockIdx.x;      // heavy tiles first
    const int bh = blockIdx.y;
    const int q0 = qt * 128;
    const int nk = 2 * qt + 2;

    const size_t tbase = (size_t)bh * TSEQ * DQK;
    const size_t vbase = (size_t)bh * DV * TSEQ;

    // ---- loaders ----
    {   // Q (group 0)
        for (int i = tid; i < 128 * 24; i += 256) {
            int row = i / 24, c = i % 24;
            uint32_t sw = (uint32_t)(row * 384 + ((c ^ (row & 7)) << 4));
            size_t g = tbase + (size_t)(q0 + row) * DQK + c * 8;
            cp16(S0 + sw, qh + g);
            cp16(S0 + QPL + sw, ql + g);
        }
        asm volatile("cp.async.commit_group;" ::: "memory");
    }
    auto loadK = [&](int it) {
        uint32_t d = S0 + 2 * QPL + (uint32_t)(it & 1) * KSTG;
        int k0 = it * 64;
        for (int i = tid; i < 64 * 24; i += 256) {
            int row = i / 24, c = i % 24;
            uint32_t sw = (uint32_t)(row * 384 + ((c ^ (row & 7)) << 4));
            size_t g = tbase + (size_t)(k0 + row) * DQK + c * 8;
            cp16(d + sw, kh + g);
            cp16(d + KPL + sw, kl + g);
        }
        asm volatile("cp.async.commit_group;" ::: "memory");
    };
    auto loadV = [&](int it) {
        uint32_t d = S0 + 2 * QPL + 2 * KSTG;
        int k0 = it * 64;
        for (int i = tid; i < 128 * 8; i += 256) {
            int row = i / 8, c = i % 8;
            uint32_t sw = (uint32_t)(row * 128 + ((c ^ (row & 7)) << 4));
            size_t g = vbase + (size_t)row * TSEQ + k0 + c * 8;
            cp16(d + sw, vh + g);
            cp16(d + VPL + sw, vl + g);
        }
        asm volatile("cp.async.commit_group;" ::: "memory");
    };

    loadK(0);   // group 1

    // fragment lane mapping
    const int a_r = lane & 15, a_kh = lane >> 4;
    const int b_n = ((lane >> 4) << 3) + (lane & 7), b_kh = (lane >> 3) & 1;
    const int qrow = wid * 16 + a_r;
    const uint32_t qoff_base = S0 + qrow * 384;

    float o[16][4];
#pragma unroll
    for (int j = 0; j < 16; ++j)
#pragma unroll
        for (int q = 0; q < 4; ++q) o[j][q] = 0.f;
    float m0r = NEG_BIG, m1r = NEG_BIG, l0r = 0.f, l1r = 0.f;

    for (int it = 0; it < nk; ++it) {
        loadV(it);
        if (it + 1 < nk) loadK(it + 1);
        else asm volatile("cp.async.commit_group;" ::: "memory");
        asm volatile("cp.async.wait_group 2;" ::: "memory");
        __syncthreads();

        // ---- S = Q K^T (3-pass fp16) ----
        float s[8][4];
#pragma unroll
        for (int j = 0; j < 8; ++j)
#pragma unroll
            for (int q = 0; q < 4; ++q) s[j][q] = 0.f;

        const uint32_t Kb = S0 + 2 * QPL + (uint32_t)(it & 1) * KSTG;
#pragma unroll 4
        for (int kc = 0; kc < 12; ++kc) {
            uint32_t qa = qoff_base + ((((kc * 2 + a_kh)) ^ (qrow & 7)) << 4);
            uint32_t qhf[4], qlf[4];
            ldm4(qhf, qa);
            ldm4(qlf, qa + QPL);
#pragma unroll
            for (int np = 0; np < 4; ++np) {
                int krow = np * 16 + b_n;
                uint32_t ka = Kb + krow * 384 + (((kc * 2 + b_kh) ^ (krow & 7)) << 4);
                uint32_t khf[4], klf[4];
                ldm4(khf, ka);
                ldm4(klf, ka + KPL);
#pragma unroll
                for (int t2 = 0; t2 < 2; ++t2) {
                    mma16816(s[np * 2 + t2], qhf, &khf[t2 * 2]);
                    mma16816(s[np * 2 + t2], qhf, &klf[t2 * 2]);
                    mma16816(s[np * 2 + t2], qlf, &khf[t2 * 2]);
                }
            }
        }

        // ---- mask (last two k-tiles only) ----
        const int k0 = it * 64;
        const int r0 = q0 + wid * 16 + (lane >> 2);
        if (it >= nk - 2) {
#pragma unroll
            for (int nt = 0; nt < 8; ++nt) {
                int kcol = k0 + nt * 8 + (lane & 3) * 2;
                if (kcol     > r0)     s[nt][0] = NEG_BIG;
                if (kcol + 1 > r0)     s[nt][1] = NEG_BIG;
                if (kcol     > r0 + 8) s[nt][2] = NEG_BIG;
                if (kcol + 1 > r0 + 8) s[nt][3] = NEG_BIG;
            }
        }

        // ---- online softmax (registers + quad shfl) ----
        float mx0 = NEG_BIG, mx1 = NEG_BIG;
#pragma unroll
        for (int nt = 0; nt < 8; ++nt) {
            mx0 = fmaxf(mx0, fmaxf(s[nt][0], s[nt][1]));
            mx1 = fmaxf(mx1, fmaxf(s[nt][2], s[nt][3]));
        }
        mx0 = fmaxf(mx0, __shfl_xor_sync(0xffffffffu, mx0, 1));
        mx0 = fmaxf(mx0, __shfl_xor_sync(0xffffffffu, mx0, 2));
        mx1 = fmaxf(mx1, __shfl_xor_sync(0xffffffffu, mx1, 1));
        mx1 = fmaxf(mx1, __shfl_xor_sync(0xffffffffu, mx1, 2));
        const float mn0 = fmaxf(m0r, mx0), mn1 = fmaxf(m1r, mx1);
        const float al0 = __expf(m0r - mn0), al1 = __expf(m1r - mn1);
        m0r = mn0; m1r = mn1;

        float sum0 = 0.f, sum1 = 0.f;
        uint32_t ph[4][4], pl[4][4];
#pragma unroll
        for (int nt = 0; nt < 8; ++nt) {
            float p0 = __expf(s[nt][0] - mn0);
            float p1 = __expf(s[nt][1] - mn0);
            float p2 = __expf(s[nt][2] - mn1);
            float p3 = __expf(s[nt][3] - mn1);
            sum0 += p0 + p1;
            sum1 += p2 + p3;
            __half2 h01 = __float22half2_rn(make_float2(p0, p1));
            __half2 h23 = __float22half2_rn(make_float2(p2, p3));
            __half2 l01 = __float22half2_rn(make_float2(p0 - __low2float(h01), p1 - __high2float(h01)));
            __half2 l23 = __float22half2_rn(make_float2(p2 - __low2float(h23), p3 - __high2float(h23)));
            const int kc2 = nt >> 1, w2 = (nt & 1) * 2;
            ph[kc2][w2]     = *(uint32_t*)&h01;
            ph[kc2][w2 + 1] = *(uint32_t*)&h23;
            pl[kc2][w2]     = *(uint32_t*)&l01;
            pl[kc2][w2 + 1] = *(uint32_t*)&l23;
        }
        sum0 += __shfl_xor_sync(0xffffffffu, sum0, 1);
        sum0 += __shfl_xor_sync(0xffffffffu, sum0, 2);
        sum1 += __shfl_xor_sync(0xffffffffu, sum1, 1);
        sum1 += __shfl_xor_sync(0xffffffffu, sum1, 2);
        l0r = l0r * al0 + sum0;
        l1r = l1r * al1 + sum1;

#pragma unroll
        for (int j = 0; j < 16; ++j) {
            o[j][0] *= al0; o[j][1] *= al0;
            o[j][2] *= al1; o[j][3] *= al1;
        }

        // ---- O += P V (3-pass fp16) ----
        asm volatile("cp.async.wait_group 1;" ::: "memory");
        __syncthreads();
        const uint32_t Vb = S0 + 2 * QPL + 2 * KSTG;
#pragma unroll
        for (int nv = 0; nv < 8; ++nv) {
            int vrow = nv * 16 + b_n;
#pragma unroll
            for (int kc2 = 0; kc2 < 4; ++kc2) {
                uint32_t va = Vb + vrow * 128 + (((kc2 * 2 + b_kh) ^ (vrow & 7)) << 4);
                uint32_t vhf[4], vlf[4];
                ldm4(vhf, va);
                ldm4(vlf, va + VPL);
#pragma unroll
                for (int t2 = 0; t2 < 2; ++t2) {
                    mma16816(o[nv * 2 + t2], ph[kc2], &vhf[t2 * 2]);
                    mma16816(o[nv * 2 + t2], ph[kc2], &vlf[t2 * 2]);
                    mma16816(o[nv * 2 + t2], pl[kc2], &vhf[t2 * 2]);
                }
            }
        }
        __syncthreads();   // V buffer reuse guard
    }

    // ---- epilogue ----
    const float inv0 = 1.0f / l0r, inv1 = 1.0f / l1r;
    const int b = bh >> 4, h = bh & 15;
    const int row0 = b * TSEQ + q0 + wid * 16 + (lane >> 2);
#pragma unroll
    for (int j = 0; j < 16; ++j) {
        const int col = h * 128 + j * 8 + (lane & 3) * 2;
        *(float2*)(g_attn + (size_t)row0 * DM + col) =
            make_float2(o[j][0] * inv0, o[j][1] * inv0);
        *(float2*)(g_attn + (size_t)(row0 + 8) * DM + col) =
            make_float2(o[j][2] * inv1, o[j][3] * inv1);
    }
}

// ---------------- host-side helpers ----------------
static void run_split(const float* src, __half* hi, __half* lo, size_t n) {
    int n4 = (int)(n / 4);
    split_f16<<<(n4 + 255) / 256, 256>>>(src, hi, lo, n4);
}
static void run_conv(const float* src, __half* dst, size_t n) {
    int n4 = (int)(n / 4);
    conv_f16<<<(n4 + 255) / 256, 256>>>(src, dst, n4);
}
template<int BN>
static void run_gemm(const __half* ah, const __half* al, const __half* bh,
                     float* c, int M, int N, int K) {
    constexpr int SMEM = 2 * (2 * 128 * 128 + BN * 128);
    cudaFuncSetAttribute(gemm_mma<BN>, cudaFuncAttributeMaxDynamicSharedMemorySize, SMEM);
    gemm_mma<BN><<<dim3(N / BN, M / 128), 256, SMEM>>>(ah, al, bh, c, M, N, K);
}

extern "C" void kernel_launch(void* const* d_in, const int* in_sizes, int n_in,
                              void* d_out, int out_size) {
    const float* x      = (const float*)d_in[0];
    const float* w_q    = (const float*)d_in[1];
    const float* w_dkv  = (const float*)d_in[2];
    const float* w_ukv  = (const float*)d_in[3];
    const float* w_o    = (const float*)d_in[4];
    const float* w_qrot = (const float*)d_in[5];
    const float* w_krot = (const float*)d_in[6];
    float* out = (float*)d_out;

    float *p_qproj, *p_qrot, *p_dkv, *p_ukv, *p_krot, *p_attn;
    cudaGetSymbolAddress((void**)&p_qproj, g_qproj);
    cudaGetSymbolAddress((void**)&p_qrot,  g_qrot);
    cudaGetSymbolAddress((void**)&p_dkv,   g_dkv);
    cudaGetSymbolAddress((void**)&p_ukv,   g_ukv);
    cudaGetSymbolAddress((void**)&p_krot,  g_krot);
    cudaGetSymbolAddress((void**)&p_attn,  g_attn);

    __half *xh,*xl,*wqh,*wqrh,*wkrh,*wdh,*wuh,*woh,*dh,*dl,*ath,*atl;
    __half *pqh,*pql,*pkh,*pkl,*pvh,*pvl;
    cudaGetSymbolAddress((void**)&xh,  g_x_hi);   cudaGetSymbolAddress((void**)&xl,  g_x_lo);
    cudaGetSymbolAddress((void**)&wqh, g_wq_h);
    cudaGetSymbolAddress((void**)&wqrh,g_wqr_h);
    cudaGetSymbolAddress((void**)&wkrh,g_wkr_h);
    cudaGetSymbolAddress((void**)&wdh, g_wdkv_h);
    cudaGetSymbolAddress((void**)&wuh, g_wukv_h);
    cudaGetSymbolAddress((void**)&woh, g_wo_h);
    cudaGetSymbolAddress((void**)&dh,  g_dkv_hi); cudaGetSymbolAddress((void**)&dl,  g_dkv_lo);
    cudaGetSymbolAddress((void**)&ath, g_at_hi);  cudaGetSymbolAddress((void**)&atl, g_at_lo);
    cudaGetSymbolAddress((void**)&pqh, g_qh);     cudaGetSymbolAddress((void**)&pql, g_ql);
    cudaGetSymbolAddress((void**)&pkh, g_kh);     cudaGetSymbolAddress((void**)&pkl, g_kl);
    cudaGetSymbolAddress((void**)&pvh, g_vh);     cudaGetSymbolAddress((void**)&pvl, g_vl);

    run_split(x, xh, xl, (size_t)BT * DM);                 // 0
    run_conv(w_q,    wqh,  (size_t)DM * DM);               // 1
    run_conv(w_qrot, wqrh, (size_t)1024 * DM);             // 2
    run_gemm<128>(xh, xl, wqh, p_qproj, BT, DM, DM);       // 3  <- profiled
    run_conv(w_krot, wkrh, (size_t)64 * DM);               // 4
    run_conv(w_dkv,  wdh,  (size_t)512 * DM);              // 5
    run_conv(w_ukv,  wuh,  (size_t)4096 * 512);            // 6
    run_conv(w_o,    woh,  (size_t)DM * DM);               // 7
    run_gemm<128>(xh, xl, wqrh, p_qrot, BT, 1024, DM);     // 8
    run_gemm<64> (xh, xl, wkrh, p_krot, BT, 64,   DM);     // 9
    run_gemm<128>(xh, xl, wdh,  p_dkv,  BT, 512,  DM);     // 10
    run_split(p_dkv, dh, dl, (size_t)BT * 512);            // 11
    run_gemm<128>(dh, dl, wuh, p_ukv, BT, 4096, 512);      // 12

    rope_kernel<<<(BT * 16 * 32 + 255) / 256, 256>>>(p_qrot, BT * 16, 16);
    rope_kernel<<<(BT * 32 + 255) / 256, 256>>>(p_krot, BT, 1);

    // pack fp16 attention operands
    const int npk = 32 * TSEQ * 24;
    pack_q<<<npk / 256, 256>>>(p_qproj, p_qrot, pqh, pql);
    pack_k<<<npk / 256, 256>>>(p_ukv, p_krot, pkh, pkl);
    pack_vt<<<dim3(TSEQ / 32, DV / 32, 32), dim3(32, 8)>>>(p_ukv, pvh, pvl);

    // tensor-core attention
    cudaFuncSetAttribute(attn_mma, cudaFuncAttributeMaxDynamicSharedMemorySize, ATT_SMEM);
    attn_mma<<<dim3(TSEQ / 128, 32), 256, ATT_SMEM>>>(pqh, pql, pkh, pkl, pvh, pvl);

    // output projection
    run_split(p_attn, ath, atl, (size_t)BT * DM);
    run_gemm<128>(ath, atl, woh, out, BT, DM, DM);
}

// round 6
// speedup vs baseline: 5.5269x; 1.1605x over previous
#include <cuda_runtime.h>
#include <cuda_fp16.h>
#include <math.h>
#include <cstdint>

#define BT    4096
#define TSEQ  2048
#define DM    2048
#define DQK   192
#define DV    128
#define ATT_SCALE 0.07216878364870323f   // 1/sqrt(192)
#define NEG_BIG  -1e30f

// ---------------- fp32 scratch ----------------
__device__ float g_qproj[BT * DM];
__device__ float g_qrot [BT * 1024];
__device__ float g_ukv  [BT * 4096];
__device__ float g_krot [BT * 64];
// ---------------- fp16 gemm operands ----------------
__device__ __half g_x_hi[BT*DM],   g_x_lo[BT*DM];
__device__ __half g_wq_h[DM*DM];
__device__ __half g_wqr_h[1024*DM];
__device__ __half g_wkr_h[64*DM];
__device__ __half g_wdkv_h[512*DM];
__device__ __half g_wukv_h[4096*512];
__device__ __half g_wo_h[DM*DM];
__device__ __half g_dkv_hi[BT*512], g_dkv_lo[BT*512];
__device__ __half g_at_hi[BT*DM],   g_at_lo[BT*DM];
// ---------------- fp16 attention operands (packed per (b,h)) ----------------
__device__ __half g_qh[32*TSEQ*DQK], g_ql[32*TSEQ*DQK];   // [bh][t][192], SCALE folded
__device__ __half g_kh[32*TSEQ*DQK];                      // [bh][t][192] (single)
__device__ __half g_vh[32*DV*TSEQ];                       // [bh][dv][t]  (single, transposed)

// ---------------- PTX helpers ----------------
__device__ __forceinline__ void cp16(uint32_t s, const void* g) {
    asm volatile("cp.async.cg.shared.global [%0], [%1], 16;" :: "r"(s), "l"(g) : "memory");
}
__device__ __forceinline__ uint32_t smem_u32(const void* p) {
    uint32_t a;
    asm("{ .reg .u64 t; cvta.to.shared.u64 t, %1; cvt.u32.u64 %0, t; }" : "=r"(a) : "l"(p));
    return a;
}
__device__ __forceinline__ void ldm4(uint32_t* r, uint32_t addr) {
    asm volatile("ldmatrix.sync.aligned.m8n8.x4.shared.b16 {%0,%1,%2,%3}, [%4];"
        : "=r"(r[0]), "=r"(r[1]), "=r"(r[2]), "=r"(r[3]) : "r"(addr));
}
__device__ __forceinline__ void mma16816(float* c, const uint32_t* a, const uint32_t* b) {
    asm volatile(
        "mma.sync.aligned.m16n8k16.row.col.f32.f16.f16.f32 "
        "{%0,%1,%2,%3}, {%4,%5,%6,%7}, {%8,%9}, {%0,%1,%2,%3};"
        : "+f"(c[0]), "+f"(c[1]), "+f"(c[2]), "+f"(c[3])
        : "r"(a[0]), "r"(a[1]), "r"(a[2]), "r"(a[3]), "r"(b[0]), "r"(b[1]));
}

// ---------------- fp32 -> fp16 hi/lo split / convert ----------------
__global__ void split_f16(const float* __restrict__ in, __half* __restrict__ hi,
                          __half* __restrict__ lo, int n4) {
    int i = blockIdx.x * blockDim.x + threadIdx.x;
    if (i >= n4) return;
    float4 v = ((const float4*)in)[i];
    float a[4] = {v.x, v.y, v.z, v.w};
    __half h[4], l[4];
#pragma unroll
    for (int k = 0; k < 4; ++k) {
        h[k] = __float2half_rn(a[k]);
        l[k] = __float2half_rn(a[k] - __half2float(h[k]));
    }
    ((__half2*)hi)[i*2]   = __halves2half2(h[0], h[1]);
    ((__half2*)hi)[i*2+1] = __halves2half2(h[2], h[3]);
    ((__half2*)lo)[i*2]   = __halves2half2(l[0], l[1]);
    ((__half2*)lo)[i*2+1] = __halves2half2(l[2], l[3]);
}
__global__ void conv_f16(const float* __restrict__ in, __half* __restrict__ out, int n4) {
    int i = blockIdx.x * blockDim.x + threadIdx.x;
    if (i >= n4) return;
    float4 v = ((const float4*)in)[i];
    ((__half2*)out)[i*2]   = __halves2half2(__float2half_rn(v.x), __float2half_rn(v.y));
    ((__half2*)out)[i*2+1] = __halves2half2(__float2half_rn(v.z), __float2half_rn(v.w));
}

// ---------------- fp16x2 NT GEMM via mma.sync (fp32 or split-fp16 output) ----------------
template<int BN, bool SPLIT>
__global__ __launch_bounds__(256, 2)
void gemm_mma(const __half* __restrict__ Ah, const __half* __restrict__ Al,
              const __half* __restrict__ Bh,
              float* __restrict__ C, __half* __restrict__ CH, __half* __restrict__ CL,
              int M, int N, int K)
{
    constexpr int ATILE = 128 * 128;
    constexpr int BTILE = BN * 128;
    constexpr int STG   = 2 * ATILE + BTILE;
    constexpr int WN = (BN == 128) ? 4 : 2;
    constexpr int WTM = 128 / (8 / WN);
    constexpr int MT = WTM / 16;
    constexpr int NT = 4;

    extern __shared__ __align__(128) char smem[];
    const uint32_t d0 = smem_u32(smem);

    const int tid = threadIdx.x;
    const int wid = tid >> 5, lane = tid & 31;
    const int wn = wid % WN, wm = wid / WN;
    const int m0 = blockIdx.y * 128;
    const int n0 = blockIdx.x * BN;
    const int l7 = lane & 7;

    float acc[MT][NT][4];
#pragma unroll
    for (int i = 0; i < MT; ++i)
#pragma unroll
        for (int j = 0; j < NT; ++j)
#pragma unroll
            for (int q = 0; q < 4; ++q) acc[i][j][q] = 0.f;

    uint32_t arow[MT], brow[NT / 2];
    const int a_r = lane & 15;
    const int a_kh = lane >> 4;
    const int b_n = ((lane >> 4) << 3) + (lane & 7);
    const int b_kh = (lane >> 3) & 1;
#pragma unroll
    for (int mt = 0; mt < MT; ++mt) arow[mt] = (uint32_t)((wm * WTM + mt * 16 + a_r) * 128);
#pragma unroll
    for (int np = 0; np < NT / 2; ++np) brow[np] = (uint32_t)((wn * 32 + np * 16 + b_n) * 128);

    auto load_tile = [&](int t, int s) {
        const uint32_t d = d0 + (uint32_t)s * STG;
        const int k0 = t * 64;
#pragma unroll
        for (int j = 0; j < 4; ++j) {
            const int c = tid + j * 256;
            const int row = c >> 3, ch = c & 7;
            const uint32_t sw = (uint32_t)(row * 128 + ((ch ^ (row & 7)) << 4));
            const size_t g = (size_t)(m0 + row) * K + k0 + ch * 8;
            cp16(d + sw, Ah + g);
            cp16(d + ATILE + sw, Al + g);
        }
#pragma unroll
        for (int j = 0; j < BN / 32; ++j) {
            const int c = tid + j * 256;
            const int row = c >> 3, ch = c & 7;
            const uint32_t sw = (uint32_t)(row * 128 + ((ch ^ (row & 7)) << 4));
            const size_t g = (size_t)(n0 + row) * K + k0 + ch * 8;
            cp16(d + 2 * ATILE + sw, Bh + g);
        }
        asm volatile("cp.async.commit_group;" ::: "memory");
    };

    const int T = K >> 6;
    load_tile(0, 0);
    if (T > 1) load_tile(1, 1);

    for (int t = 0; t < T; ++t) {
        const int s = t & 1;
        if (t + 1 < T) asm volatile("cp.async.wait_group 1;" ::: "memory");
        else           asm volatile("cp.async.wait_group 0;" ::: "memory");
        __syncthreads();

        const uint32_t AhS = d0 + (uint32_t)s * STG;
        const uint32_t AlS = AhS + ATILE;
        const uint32_t BhS = AhS + 2 * ATILE;

#pragma unroll
        for (int kk = 0; kk < 4; ++kk) {
            const uint32_t aoff = (uint32_t)(((kk * 2 + a_kh) ^ l7) << 4);
            const uint32_t boff = (uint32_t)(((kk * 2 + b_kh) ^ l7) << 4);
            uint32_t ah[MT][4], al[MT][4], bh[NT / 2][4];
#pragma unroll
            for (int mt = 0; mt < MT; ++mt) {
                ldm4(ah[mt], AhS + arow[mt] + aoff);
                ldm4(al[mt], AlS + arow[mt] + aoff);
            }
#pragma unroll
            for (int np = 0; np < NT / 2; ++np)
                ldm4(bh[np], BhS + brow[np] + boff);
#pragma unroll
            for (int mt = 0; mt < MT; ++mt)
#pragma unroll
                for (int nt = 0; nt < NT; ++nt) {
                    const uint32_t* bhp = &bh[nt >> 1][(nt & 1) * 2];
                    mma16816(acc[mt][nt], ah[mt], bhp);
                    mma16816(acc[mt][nt], al[mt], bhp);
                }
        }
        __syncthreads();
        if (t + 2 < T) load_tile(t + 2, s);
    }

    const int cr = lane >> 2;
    const int cc = (lane & 3) * 2;
#pragma unroll
    for (int mt = 0; mt < MT; ++mt) {
        const int r0 = m0 + wm * WTM + mt * 16 + cr;
#pragma unroll
        for (int nt = 0; nt < NT; ++nt) {
            const int col = n0 + wn * 32 + nt * 8 + cc;
            if constexpr (SPLIT) {
#pragma unroll
                for (int half = 0; half < 2; ++half) {
                    float2 v = make_float2(acc[mt][nt][half*2], acc[mt][nt][half*2+1]);
                    __half2 h2 = __float22half2_rn(v);
                    __half2 l2 = __float22half2_rn(
                        make_float2(v.x - __low2float(h2), v.y - __high2float(h2)));
                    const size_t off = (size_t)(r0 + half * 8) * N + col;
                    *(__half2*)(CH + off) = h2;
                    *(__half2*)(CL + off) = l2;
                }
            } else {
                *(float2*)(C + (size_t)r0 * N + col)       = make_float2(acc[mt][nt][0], acc[mt][nt][1]);
                *(float2*)(C + (size_t)(r0 + 8) * N + col) = make_float2(acc[mt][nt][2], acc[mt][nt][3]);
            }
        }
    }
}

// ---------------- RoPE (in place) ----------------
__global__ void rope_kernel(float* __restrict__ d, int nvec, int vecs_per_row) {
    const int idx = blockIdx.x * blockDim.x + threadIdx.x;
    if (idx >= nvec * 32) return;
    const int i = idx & 31;
    const int vec = idx >> 5;
    const int row = vec / vecs_per_row;
    const int t = row & (TSEQ - 1);
    float* base = d + (size_t)vec * 64;
    const float invf = (float)exp2(-(double)i * (13.287712379549449 / 32.0));
    const float angf = (float)t * invf;
    double sd, cd;
    sincos((double)angf, &sd, &cd);
    const float s = (float)sd, c = (float)cd;
    const float x1 = base[i], x2 = base[i + 32];
    base[i]      = x1 * c - x2 * s;
    base[i + 32] = x2 * c + x1 * s;
}

// ---------------- pack helpers ----------------
__device__ __forceinline__ void split8_store(const float* v, __half* oh, __half* ol, size_t off) {
    uint4 uh, ul;
    uint32_t* ph = (uint32_t*)&uh;
    uint32_t* pl = (uint32_t*)&ul;
#pragma unroll
    for (int q = 0; q < 4; ++q) {
        float2 f = make_float2(v[2*q], v[2*q+1]);
        __half2 h = __float22half2_rn(f);
        float2 r = make_float2(f.x - __low2float(h), f.y - __high2float(h));
        __half2 l = __float22half2_rn(r);
        ph[q] = *(uint32_t*)&h;
        pl[q] = *(uint32_t*)&l;
    }
    *(uint4*)(oh + off) = uh;
    *(uint4*)(ol + off) = ul;
}
__device__ __forceinline__ void conv8_store(const float* v, __half* oh, size_t off) {
    uint4 uh;
    uint32_t* ph = (uint32_t*)&uh;
#pragma unroll
    for (int q = 0; q < 4; ++q) {
        __half2 h = __float22half2_rn(make_float2(v[2*q], v[2*q+1]));
        ph[q] = *(uint32_t*)&h;
    }
    *(uint4*)(oh + off) = uh;
}

// q: gather qproj/qrot (roped), fold SCALE, split hi/lo -> [bh][t][192]
__global__ void pack_q(const float* __restrict__ qp, const float* __restrict__ qr,
                       __half* __restrict__ oh, __half* __restrict__ ol) {
    int i = blockIdx.x * blockDim.x + threadIdx.x;
    int c8 = i % 24;
    int mt = i / 24;
    int bh = mt >> 11, t = mt & 2047;
    int b = bh >> 4, h = bh & 15;
    size_t m = (size_t)b * TSEQ + t;
    float v[8];
    if (c8 < 16) {
        const float4* p = (const float4*)(qp + m * DM + h * 128 + c8 * 8);
        float4 a = p[0], bq = p[1];
        v[0]=a.x; v[1]=a.y; v[2]=a.z; v[3]=a.w; v[4]=bq.x; v[5]=bq.y; v[6]=bq.z; v[7]=bq.w;
    } else {
        const float4* p = (const float4*)(qr + m * 1024 + h * 64 + (c8 - 16) * 8);
        float4 a = p[0], bq = p[1];
        v[0]=a.x; v[1]=a.y; v[2]=a.z; v[3]=a.w; v[4]=bq.x; v[5]=bq.y; v[6]=bq.z; v[7]=bq.w;
    }
#pragma unroll
    for (int q = 0; q < 8; ++q) v[q] *= ATT_SCALE;
    split8_store(v, oh, ol, ((size_t)bh * TSEQ + t) * DQK + c8 * 8);
}

// k: gather ukv/krot (roped), single fp16 -> [bh][t][192]
__global__ void pack_k(const float* __restrict__ ukv, const float* __restrict__ kr,
                       __half* __restrict__ oh) {
    int i = blockIdx.x * blockDim.x + threadIdx.x;
    int c8 = i % 24;
    int mt = i / 24;
    int bh = mt >> 11, t = mt & 2047;
    int b = bh >> 4, h = bh & 15;
    size_t m = (size_t)b * TSEQ + t;
    float v[8];
    if (c8 < 16) {
        const float4* p = (const float4*)(ukv + m * 4096 + h * 256 + c8 * 8);
        float4 a = p[0], bq = p[1];
        v[0]=a.x; v[1]=a.y; v[2]=a.z; v[3]=a.w; v[4]=bq.x; v[5]=bq.y; v[6]=bq.z; v[7]=bq.w;
    } else {
        const float4* p = (const float4*)(kr + m * 64 + (c8 - 16) * 8);
        float4 a = p[0], bq = p[1];
        v[0]=a.x; v[1]=a.y; v[2]=a.z; v[3]=a.w; v[4]=bq.x; v[5]=bq.y; v[6]=bq.z; v[7]=bq.w;
    }
    conv8_store(v, oh, ((size_t)bh * TSEQ + t) * DQK + c8 * 8);
}

// v: transpose [t][dv] -> [bh][dv][t], single fp16
__global__ void pack_vt(const float* __restrict__ ukv, __half* __restrict__ oh) {
    __shared__ float tile[32][33];
    int t0 = blockIdx.x * 32, c0 = blockIdx.y * 32, bh = blockIdx.z;
    int b = bh >> 4, h = bh & 15;
    int tx = threadIdx.x, ty = threadIdx.y;
#pragma unroll
    for (int j = 0; j < 4; ++j) {
        int t = t0 + ty + j * 8;
        tile[ty + j * 8][tx] = ukv[((size_t)b * TSEQ + t) * 4096 + h * 256 + 128 + c0 + tx];
    }
    __syncthreads();
#pragma unroll
    for (int j = 0; j < 4; ++j) {
        int c = c0 + ty + j * 8;
        oh[((size_t)bh * DV + c) * TSEQ + t0 + tx] = __float2half_rn(tile[tx][ty + j * 8]);
    }
}

// ---------------- tensor-core flash attention ----------------
// BQ=128, BK=64, 8 warps. Q hi/lo in smem; K(single)+V(single) double-buffered.
#define QPL  49152           // 128 rows x 384B
#define KPL  24576           // 64 x 384B (single plane)
#define VPL  16384           // 128 x 128B
#define KVSTG (KPL + VPL)    // 40960
#define ATT_SMEM (2*QPL + 2*KVSTG)   // 180224

__global__ __launch_bounds__(256, 1) void attn_mma(
    const __half* __restrict__ qh, const __half* __restrict__ ql,
    const __half* __restrict__ kh, const __half* __restrict__ vh,
    __half* __restrict__ outh, __half* __restrict__ outl)
{
    extern __shared__ __align__(128) char smem[];
    const uint32_t S0 = smem_u32(smem);
    const int tid = threadIdx.x, wid = tid >> 5, lane = tid & 31;
    const int qt = gridDim.x - 1 - blockIdx.x;      // heavy tiles first
    const int bh = blockIdx.y;
    const int q0 = qt * 128;
    const int nk = 2 * qt + 2;

    const size_t tbase = (size_t)bh * TSEQ * DQK;
    const size_t vbase = (size_t)bh * DV * TSEQ;

    {   // Q (group 0)
        for (int i = tid; i < 128 * 24; i += 256) {
            int row = i / 24, c = i % 24;
            uint32_t sw = (uint32_t)(row * 384 + ((c ^ (row & 7)) << 4));
            size_t g = tbase + (size_t)(q0 + row) * DQK + c * 8;
            cp16(S0 + sw, qh + g);
            cp16(S0 + QPL + sw, ql + g);
        }
        asm volatile("cp.async.commit_group;" ::: "memory");
    }
    auto loadKV = [&](int it) {
        if (it < nk) {
            uint32_t d = S0 + 2 * QPL + (uint32_t)(it & 1) * KVSTG;
            int k0 = it * 64;
            for (int i = tid; i < 64 * 24; i += 256) {
                int row = i / 24, c = i % 24;
                uint32_t sw = (uint32_t)(row * 384 + ((c ^ (row & 7)) << 4));
                cp16(d + sw, kh + tbase + (size_t)(k0 + row) * DQK + c * 8);
            }
            uint32_t dv = d + KPL;
            for (int i = tid; i < 128 * 8; i += 256) {
                int row = i / 8, c = i % 8;
                uint32_t sw = (uint32_t)(row * 128 + ((c ^ (row & 7)) << 4));
                cp16(dv + sw, vh + vbase + (size_t)row * TSEQ + k0 + c * 8);
            }
        }
        asm volatile("cp.async.commit_group;" ::: "memory");
    };

    loadKV(0);   // group 1
    loadKV(1);   // group 2

    const int a_r = lane & 15, a_kh = lane >> 4;
    const int b_n = ((lane >> 4) << 3) + (lane & 7), b_kh = (lane >> 3) & 1;
    const int qrow = wid * 16 + a_r;
    const uint32_t qoff_base = S0 + qrow * 384;

    float o[16][4];
#pragma unroll
    for (int j = 0; j < 16; ++j)
#pragma unroll
        for (int q = 0; q < 4; ++q) o[j][q] = 0.f;
    float m0r = NEG_BIG, m1r = NEG_BIG, l0r = 0.f, l1r = 0.f;

    for (int it = 0; it < nk; ++it) {
        asm volatile("cp.async.wait_group 1;" ::: "memory");
        __syncthreads();

        const uint32_t Kb = S0 + 2 * QPL + (uint32_t)(it & 1) * KVSTG;
        const uint32_t Vb = Kb + KPL;

        // ---- S = Q K^T (Qh + Ql, K single) ----
        float s[8][4];
#pragma unroll
        for (int j = 0; j < 8; ++j)
#pragma unroll
            for (int q = 0; q < 4; ++q) s[j][q] = 0.f;

#pragma unroll 4
        for (int kc = 0; kc < 12; ++kc) {
            uint32_t qa = qoff_base + ((((kc * 2 + a_kh)) ^ (qrow & 7)) << 4);
            uint32_t qhf[4], qlf[4];
            ldm4(qhf, qa);
            ldm4(qlf, qa + QPL);
#pragma unroll
            for (int np = 0; np < 4; ++np) {
                int krow = np * 16 + b_n;
                uint32_t ka = Kb + krow * 384 + (((kc * 2 + b_kh) ^ (krow & 7)) << 4);
                uint32_t khf[4];
                ldm4(khf, ka);
#pragma unroll
                for (int t2 = 0; t2 < 2; ++t2) {
                    mma16816(s[np * 2 + t2], qhf, &khf[t2 * 2]);
                    mma16816(s[np * 2 + t2], qlf, &khf[t2 * 2]);
                }
            }
        }

        // ---- mask (last two k-tiles only) ----
        const int k0 = it * 64;
        const int r0 = q0 + wid * 16 + (lane >> 2);
        if (it >= nk - 2) {
#pragma unroll
            for (int nt = 0; nt < 8; ++nt) {
                int kcol = k0 + nt * 8 + (lane & 3) * 2;
                if (kcol     > r0)     s[nt][0] = NEG_BIG;
                if (kcol + 1 > r0)     s[nt][1] = NEG_BIG;
                if (kcol     > r0 + 8) s[nt][2] = NEG_BIG;
                if (kcol + 1 > r0 + 8) s[nt][3] = NEG_BIG;
            }
        }

        // ---- online softmax ----
        float mx0 = NEG_BIG, mx1 = NEG_BIG;
#pragma unroll
        for (int nt = 0; nt < 8; ++nt) {
            mx0 = fmaxf(mx0, fmaxf(s[nt][0], s[nt][1]));
            mx1 = fmaxf(mx1, fmaxf(s[nt][2], s[nt][3]));
        }
        mx0 = fmaxf(mx0, __shfl_xor_sync(0xffffffffu, mx0, 1));
        mx0 = fmaxf(mx0, __shfl_xor_sync(0xffffffffu, mx0, 2));
        mx1 = fmaxf(mx1, __shfl_xor_sync(0xffffffffu, mx1, 1));
        mx1 = fmaxf(mx1, __shfl_xor_sync(0xffffffffu, mx1, 2));
        const float mn0 = fmaxf(m0r, mx0), mn1 = fmaxf(m1r, mx1);
        const float al0 = __expf(m0r - mn0), al1 = __expf(m1r - mn1);
        m0r = mn0; m1r = mn1;

        float sum0 = 0.f, sum1 = 0.f;
        uint32_t ph[4][4];
#pragma unroll
        for (int nt = 0; nt < 8; ++nt) {
            float p0 = __expf(s[nt][0] - mn0);
            float p1 = __expf(s[nt][1] - mn0);
            float p2 = __expf(s[nt][2] - mn1);
            float p3 = __expf(s[nt][3] - mn1);
            sum0 += p0 + p1;
            sum1 += p2 + p3;
            __half2 h01 = __float22half2_rn(make_float2(p0, p1));
            __half2 h23 = __float22half2_rn(make_float2(p2, p3));
            const int kc2 = nt >> 1, w2 = (nt & 1) * 2;
            ph[kc2][w2]     = *(uint32_t*)&h01;
            ph[kc2][w2 + 1] = *(uint32_t*)&h23;
        }
        sum0 += __shfl_xor_sync(0xffffffffu, sum0, 1);
        sum0 += __shfl_xor_sync(0xffffffffu, sum0, 2);
        sum1 += __shfl_xor_sync(0xffffffffu, sum1, 1);
        sum1 += __shfl_xor_sync(0xffffffffu, sum1, 2);
        l0r = l0r * al0 + sum0;
        l1r = l1r * al1 + sum1;

#pragma unroll
        for (int j = 0; j < 16; ++j) {
            o[j][0] *= al0; o[j][1] *= al0;
            o[j][2] *= al1; o[j][3] *= al1;
        }

        // ---- O += P V (single pass) ----
#pragma unroll
        for (int nv = 0; nv < 8; ++nv) {
            int vrow = nv * 16 + b_n;
#pragma unroll
            for (int kc2 = 0; kc2 < 4; ++kc2) {
                uint32_t va = Vb + vrow * 128 + (((kc2 * 2 + b_kh) ^ (vrow & 7)) << 4);
                uint32_t vhf[4];
                ldm4(vhf, va);
#pragma unroll
                for (int t2 = 0; t2 < 2; ++t2)
                    mma16816(o[nv * 2 + t2], ph[kc2], &vhf[t2 * 2]);
            }
        }
        __syncthreads();      // slot (it&1) fully consumed before reload
        loadKV(it + 2);
    }

    // ---- epilogue: write fp16 hi/lo directly ----
    const float inv0 = 1.0f / l0r, inv1 = 1.0f / l1r;
    const int b = bh >> 4, h = bh & 15;
    const int row0 = b * TSEQ + q0 + wid * 16 + (lane >> 2);
#pragma unroll
    for (int j = 0; j < 16; ++j) {
        const int col = h * 128 + j * 8 + (lane & 3) * 2;
#pragma unroll
        for (int half = 0; half < 2; ++half) {
            float2 v = half ? make_float2(o[j][2] * inv1, o[j][3] * inv1)
                            : make_float2(o[j][0] * inv0, o[j][1] * inv0);
            __half2 h2 = __float22half2_rn(v);
            __half2 l2 = __float22half2_rn(
                make_float2(v.x - __low2float(h2), v.y - __high2float(h2)));
            const size_t off = (size_t)(row0 + half * 8) * DM + col;
            *(__half2*)(outh + off) = h2;
            *(__half2*)(outl + off) = l2;
        }
    }
}

// ---------------- host-side helpers ----------------
static void run_split(const float* src, __half* hi, __half* lo, size_t n) {
    int n4 = (int)(n / 4);
    split_f16<<<(n4 + 255) / 256, 256>>>(src, hi, lo, n4);
}
static void run_conv(const float* src, __half* dst, size_t n) {
    int n4 = (int)(n / 4);
    conv_f16<<<(n4 + 255) / 256, 256>>>(src, dst, n4);
}
template<int BN>
static void run_gemm(const __half* ah, const __half* al, const __half* bh,
                     float* c, int M, int N, int K) {
    constexpr int SMEM = 2 * (2 * 128 * 128 + BN * 128);
    cudaFuncSetAttribute(gemm_mma<BN, false>, cudaFuncAttributeMaxDynamicSharedMemorySize, SMEM);
    gemm_mma<BN, false><<<dim3(N / BN, M / 128), 256, SMEM>>>(ah, al, bh, c, nullptr, nullptr, M, N, K);
}
template<int BN>
static void run_gemm_split(const __half* ah, const __half* al, const __half* bh,
                           __half* ch, __half* cl, int M, int N, int K) {
    constexpr int SMEM = 2 * (2 * 128 * 128 + BN * 128);
    cudaFuncSetAttribute(gemm_mma<BN, true>, cudaFuncAttributeMaxDynamicSharedMemorySize, SMEM);
    gemm_mma<BN, true><<<dim3(N / BN, M / 128), 256, SMEM>>>(ah, al, bh, nullptr, ch, cl, M, N, K);
}

extern "C" void kernel_launch(void* const* d_in, const int* in_sizes, int n_in,
                              void* d_out, int out_size) {
    const float* x      = (const float*)d_in[0];
    const float* w_q    = (const float*)d_in[1];
    const float* w_dkv  = (const float*)d_in[2];
    const float* w_ukv  = (const float*)d_in[3];
    const float* w_o    = (const float*)d_in[4];
    const float* w_qrot = (const float*)d_in[5];
    const float* w_krot = (const float*)d_in[6];
    float* out = (float*)d_out;

    float *p_qproj, *p_qrot, *p_ukv, *p_krot;
    cudaGetSymbolAddress((void**)&p_qproj, g_qproj);
    cudaGetSymbolAddress((void**)&p_qrot,  g_qrot);
    cudaGetSymbolAddress((void**)&p_ukv,   g_ukv);
    cudaGetSymbolAddress((void**)&p_krot,  g_krot);

    __half *xh,*xl,*wqh,*wqrh,*wkrh,*wdh,*wuh,*woh,*dh,*dl,*ath,*atl;
    __half *pqh,*pql,*pkh,*pvh;
    cudaGetSymbolAddress((void**)&xh,  g_x_hi);   cudaGetSymbolAddress((void**)&xl,  g_x_lo);
    cudaGetSymbolAddress((void**)&wqh, g_wq_h);
    cudaGetSymbolAddress((void**)&wqrh,g_wqr_h);
    cudaGetSymbolAddress((void**)&wkrh,g_wkr_h);
    cudaGetSymbolAddress((void**)&wdh, g_wdkv_h);
    cudaGetSymbolAddress((void**)&wuh, g_wukv_h);
    cudaGetSymbolAddress((void**)&woh, g_wo_h);
    cudaGetSymbolAddress((void**)&dh,  g_dkv_hi); cudaGetSymbolAddress((void**)&dl,  g_dkv_lo);
    cudaGetSymbolAddress((void**)&ath, g_at_hi);  cudaGetSymbolAddress((void**)&atl, g_at_lo);
    cudaGetSymbolAddress((void**)&pqh, g_qh);     cudaGetSymbolAddress((void**)&pql, g_ql);
    cudaGetSymbolAddress((void**)&pkh, g_kh);
    cudaGetSymbolAddress((void**)&pvh, g_vh);

    run_split(x, xh, xl, (size_t)BT * DM);                 // 0
    run_conv(w_q,    wqh,  (size_t)DM * DM);               // 1
    run_conv(w_qrot, wqrh, (size_t)1024 * DM);             // 2
    run_gemm<128>(xh, xl, wqh, p_qproj, BT, DM, DM);       // 3  <- profiled
    run_conv(w_krot, wkrh, (size_t)64 * DM);               // 4
    run_conv(w_dkv,  wdh,  (size_t)512 * DM);              // 5
    run_conv(w_ukv,  wuh,  (size_t)4096 * 512);            // 6
    run_conv(w_o,    woh,  (size_t)DM * DM);               // 7
    run_gemm<128>(xh, xl, wqrh, p_qrot, BT, 1024, DM);     // 8
    run_gemm<64> (xh, xl, wkrh, p_krot, BT, 64,   DM);     // 9
    run_gemm_split<128>(xh, xl, wdh, dh, dl, BT, 512, DM); // 10 (split epilogue)
    run_gemm<128>(dh, dl, wuh, p_ukv, BT, 4096, 512);      // 11

    rope_kernel<<<(BT * 16 * 32 + 255) / 256, 256>>>(p_qrot, BT * 16, 16);
    rope_kernel<<<(BT * 32 + 255) / 256, 256>>>(p_krot, BT, 1);

    const int npk = 32 * TSEQ * 24;
    pack_q<<<npk / 256, 256>>>(p_qproj, p_qrot, pqh, pql);
    pack_k<<<npk / 256, 256>>>(p_ukv, p_krot, pkh);
    pack_vt<<<dim3(TSEQ / 32, DV / 32, 32), dim3(32, 8)>>>(p_ukv, pvh);

    cudaFuncSetAttribute(attn_mma, cudaFuncAttributeMaxDynamicSharedMemorySize, ATT_SMEM);
    attn_mma<<<dim3(TSEQ / 128, 32), 256, ATT_SMEM>>>(pqh, pql, pkh, pvh, ath, atl);

    run_gemm<128>(ath, atl, woh, out, BT, DM, DM);
}

// round 7
// speedup vs baseline: 7.7274x; 1.3981x over previous
#include <cuda_runtime.h>
#include <cuda_fp16.h>
#include <math.h>
#include <cstdint>

#define BT    4096
#define TSEQ  2048
#define DM    2048
#define DQK   192
#define DV    128
#define ATT_SCALE 0.07216878364870323f   // 1/sqrt(192)
#define NEG_BIG  -1e30f

// ---------------- scratch ----------------
__device__ float  g_qrot [BT * 1024];     // fp32 (roped in place, pre-scaled)
__device__ float  g_krot [BT * 64];       // fp32 (roped in place)
__device__ __half g_qproj[BT * DM];       // fp16 (pre-scaled)
__device__ __half g_dkv  [BT * 512];
__device__ __half g_ukv  [BT * 4096];
__device__ __half g_attn [BT * DM];
__device__ __half g_x    [BT * DM];
__device__ __half g_wq_h [DM * DM];
__device__ __half g_wqr_h[1024 * DM];
__device__ __half g_wkr_h[64 * DM];
__device__ __half g_wdkv_h[512 * DM];
__device__ __half g_wukv_h[4096 * 512];
__device__ __half g_wo_h [DM * DM];
// packed attention operands
__device__ __half g_qh[32 * TSEQ * DQK];  // [bh][t][192] (scaled)
__device__ __half g_kh[32 * TSEQ * DQK];  // [bh][t][192]
__device__ __half g_vh[32 * DV * TSEQ];   // [bh][dv][t]

// ---------------- PTX helpers ----------------
__device__ __forceinline__ void cp16(uint32_t s, const void* g) {
    asm volatile("cp.async.cg.shared.global [%0], [%1], 16;" :: "r"(s), "l"(g) : "memory");
}
__device__ __forceinline__ uint32_t smem_u32(const void* p) {
    uint32_t a;
    asm("{ .reg .u64 t; cvta.to.shared.u64 t, %1; cvt.u32.u64 %0, t; }" : "=r"(a) : "l"(p));
    return a;
}
__device__ __forceinline__ void ldm4(uint32_t* r, uint32_t addr) {
    asm volatile("ldmatrix.sync.aligned.m8n8.x4.shared.b16 {%0,%1,%2,%3}, [%4];"
        : "=r"(r[0]), "=r"(r[1]), "=r"(r[2]), "=r"(r[3]) : "r"(addr));
}
__device__ __forceinline__ void mma16816(float* c, const uint32_t* a, const uint32_t* b) {
    asm volatile(
        "mma.sync.aligned.m16n8k16.row.col.f32.f16.f16.f32 "
        "{%0,%1,%2,%3}, {%4,%5,%6,%7}, {%8,%9}, {%0,%1,%2,%3};"
        : "+f"(c[0]), "+f"(c[1]), "+f"(c[2]), "+f"(c[3])
        : "r"(a[0]), "r"(a[1]), "r"(a[2]), "r"(a[3]), "r"(b[0]), "r"(b[1]));
}

// ---------------- fp32 -> fp16 converts ----------------
__global__ void conv_f16(const float* __restrict__ in, __half* __restrict__ out, int n4) {
    int i = blockIdx.x * blockDim.x + threadIdx.x;
    if (i >= n4) return;
    float4 v = ((const float4*)in)[i];
    ((__half2*)out)[i*2]   = __halves2half2(__float2half_rn(v.x), __float2half_rn(v.y));
    ((__half2*)out)[i*2+1] = __halves2half2(__float2half_rn(v.z), __float2half_rn(v.w));
}
__global__ void conv_f16s(const float* __restrict__ in, __half* __restrict__ out, int n4) {
    int i = blockIdx.x * blockDim.x + threadIdx.x;
    if (i >= n4) return;
    float4 v = ((const float4*)in)[i];
    ((__half2*)out)[i*2]   = __halves2half2(__float2half_rn(v.x * ATT_SCALE),
                                            __float2half_rn(v.y * ATT_SCALE));
    ((__half2*)out)[i*2+1] = __halves2half2(__float2half_rn(v.z * ATT_SCALE),
                                            __float2half_rn(v.w * ATT_SCALE));
}

// ---------------- single-pass fp16 NT GEMM, 3-stage cp.async pipeline ----------------
// C[M,N] = A[M,K] * B[N,K]^T. BM=128, BK=64, 256 threads (8 warps), occ 2.
// OUT: 0 -> fp32 C, 1 -> fp16 CH.
template<int BN, int OUT>
__global__ __launch_bounds__(256, 2)
void gemm_s(const __half* __restrict__ A, const __half* __restrict__ B,
            float* __restrict__ C, __half* __restrict__ CH,
            int M, int N, int K)
{
    constexpr int ATILE = 128 * 128;   // 16 KB (128 rows x 64 fp16)
    constexpr int BTILE = BN * 128;
    constexpr int STG   = ATILE + BTILE;
    constexpr int WN = (BN == 128) ? 4 : 2;
    constexpr int WTM = 128 / (8 / WN);
    constexpr int MT = WTM / 16;
    constexpr int NT = 4;

    extern __shared__ __align__(128) char smem[];
    const uint32_t d0 = smem_u32(smem);

    const int tid = threadIdx.x;
    const int wid = tid >> 5, lane = tid & 31;
    const int wn = wid % WN, wm = wid / WN;
    const int m0 = blockIdx.y * 128;
    const int n0 = blockIdx.x * BN;
    const int l7 = lane & 7;

    float acc[MT][NT][4];
#pragma unroll
    for (int i = 0; i < MT; ++i)
#pragma unroll
        for (int j = 0; j < NT; ++j)
#pragma unroll
            for (int q = 0; q < 4; ++q) acc[i][j][q] = 0.f;

    uint32_t arow[MT], brow[NT / 2];
    const int a_r = lane & 15;
    const int a_kh = lane >> 4;
    const int b_n = ((lane >> 4) << 3) + (lane & 7);
    const int b_kh = (lane >> 3) & 1;
#pragma unroll
    for (int mt = 0; mt < MT; ++mt) arow[mt] = (uint32_t)((wm * WTM + mt * 16 + a_r) * 128);
#pragma unroll
    for (int np = 0; np < NT / 2; ++np) brow[np] = (uint32_t)((wn * 32 + np * 16 + b_n) * 128);

    const int T = K >> 6;
    auto load_tile = [&](int t) {
        if (t < T) {
            const uint32_t d = d0 + (uint32_t)(t % 3) * STG;
            const int k0 = t * 64;
#pragma unroll
            for (int j = 0; j < 4; ++j) {
                const int c = tid + j * 256;
                const int row = c >> 3, ch = c & 7;
                const uint32_t sw = (uint32_t)(row * 128 + ((ch ^ (row & 7)) << 4));
                cp16(d + sw, A + (size_t)(m0 + row) * K + k0 + ch * 8);
            }
#pragma unroll
            for (int j = 0; j < BN / 32; ++j) {
                const int c = tid + j * 256;
                const int row = c >> 3, ch = c & 7;
                const uint32_t sw = (uint32_t)(row * 128 + ((ch ^ (row & 7)) << 4));
                cp16(d + ATILE + sw, B + (size_t)(n0 + row) * K + k0 + ch * 8);
            }
        }
        asm volatile("cp.async.commit_group;" ::: "memory");
    };

    load_tile(0);
    load_tile(1);
    load_tile(2);

    for (int t = 0; t < T; ++t) {
        asm volatile("cp.async.wait_group 2;" ::: "memory");
        __syncthreads();

        const uint32_t AS = d0 + (uint32_t)(t % 3) * STG;
        const uint32_t BS = AS + ATILE;

#pragma unroll
        for (int kk = 0; kk < 4; ++kk) {
            const uint32_t aoff = (uint32_t)(((kk * 2 + a_kh) ^ l7) << 4);
            const uint32_t boff = (uint32_t)(((kk * 2 + b_kh) ^ l7) << 4);
            uint32_t af[MT][4], bf[NT / 2][4];
#pragma unroll
            for (int mt = 0; mt < MT; ++mt)
                ldm4(af[mt], AS + arow[mt] + aoff);
#pragma unroll
            for (int np = 0; np < NT / 2; ++np)
                ldm4(bf[np], BS + brow[np] + boff);
#pragma unroll
            for (int mt = 0; mt < MT; ++mt)
#pragma unroll
                for (int nt = 0; nt < NT; ++nt)
                    mma16816(acc[mt][nt], af[mt], &bf[nt >> 1][(nt & 1) * 2]);
        }
        __syncthreads();
        load_tile(t + 3);
    }

    const int cr = lane >> 2;
    const int cc = (lane & 3) * 2;
#pragma unroll
    for (int mt = 0; mt < MT; ++mt) {
        const int r0 = m0 + wm * WTM + mt * 16 + cr;
#pragma unroll
        for (int nt = 0; nt < NT; ++nt) {
            const int col = n0 + wn * 32 + nt * 8 + cc;
            if constexpr (OUT == 1) {
#pragma unroll
                for (int hf = 0; hf < 2; ++hf) {
                    __half2 h2 = __float22half2_rn(
                        make_float2(acc[mt][nt][hf*2], acc[mt][nt][hf*2+1]));
                    *(__half2*)(CH + (size_t)(r0 + hf * 8) * N + col) = h2;
                }
            } else {
                *(float2*)(C + (size_t)r0 * N + col)       = make_float2(acc[mt][nt][0], acc[mt][nt][1]);
                *(float2*)(C + (size_t)(r0 + 8) * N + col) = make_float2(acc[mt][nt][2], acc[mt][nt][3]);
            }
        }
    }
}

// ---------------- RoPE (in place, fp32) ----------------
__global__ void rope_kernel(float* __restrict__ d, int nvec, int vecs_per_row) {
    const int idx = blockIdx.x * blockDim.x + threadIdx.x;
    if (idx >= nvec * 32) return;
    const int i = idx & 31;
    const int vec = idx >> 5;
    const int row = vec / vecs_per_row;
    const int t = row & (TSEQ - 1);
    float* base = d + (size_t)vec * 64;
    const float invf = (float)exp2(-(double)i * (13.287712379549449 / 32.0));
    const float angf = (float)t * invf;
    double sd, cd;
    sincos((double)angf, &sd, &cd);
    const float s = (float)sd, c = (float)cd;
    const float x1 = base[i], x2 = base[i + 32];
    base[i]      = x1 * c - x2 * s;
    base[i + 32] = x2 * c + x1 * s;
}

// ---------------- packs ----------------
__device__ __forceinline__ void conv8_store(const float* v, __half* oh, size_t off) {
    uint4 uh;
    uint32_t* ph = (uint32_t*)&uh;
#pragma unroll
    for (int q = 0; q < 4; ++q) {
        __half2 h = __float22half2_rn(make_float2(v[2*q], v[2*q+1]));
        ph[q] = *(uint32_t*)&h;
    }
    *(uint4*)(oh + off) = uh;
}

// q: qproj fp16 (pre-scaled) copy + qrot fp32 (roped, pre-scaled) convert -> [bh][t][192]
__global__ void pack_q(const __half* __restrict__ qp, const float* __restrict__ qr,
                       __half* __restrict__ oh) {
    int i = blockIdx.x * blockDim.x + threadIdx.x;
    int c8 = i % 24;
    int mt = i / 24;
    int bh = mt >> 11, t = mt & 2047;
    int b = bh >> 4, h = bh & 15;
    size_t m = (size_t)b * TSEQ + t;
    size_t off = ((size_t)bh * TSEQ + t) * DQK + c8 * 8;
    if (c8 < 16) {
        *(uint4*)(oh + off) = *(const uint4*)(qp + m * DM + h * 128 + c8 * 8);
    } else {
        const float4* p = (const float4*)(qr + m * 1024 + h * 64 + (c8 - 16) * 8);
        float4 a = p[0], bq = p[1];
        float v[8] = {a.x, a.y, a.z, a.w, bq.x, bq.y, bq.z, bq.w};
        conv8_store(v, oh, off);
    }
}

// k: ukv fp16 copy + krot fp32 (roped) convert -> [bh][t][192]
__global__ void pack_k(const __half* __restrict__ ukv, const float* __restrict__ kr,
                       __half* __restrict__ oh) {
    int i = blockIdx.x * blockDim.x + threadIdx.x;
    int c8 = i % 24;
    int mt = i / 24;
    int bh = mt >> 11, t = mt & 2047;
    int b = bh >> 4, h = bh & 15;
    size_t m = (size_t)b * TSEQ + t;
    size_t off = ((size_t)bh * TSEQ + t) * DQK + c8 * 8;
    if (c8 < 16) {
        *(uint4*)(oh + off) = *(const uint4*)(ukv + m * 4096 + h * 256 + c8 * 8);
    } else {
        const float4* p = (const float4*)(kr + m * 64 + (c8 - 16) * 8);
        float4 a = p[0], bq = p[1];
        float v[8] = {a.x, a.y, a.z, a.w, bq.x, bq.y, bq.z, bq.w};
        conv8_store(v, oh, off);
    }
}

// v: transpose fp16 [t][dv] -> [bh][dv][t]
__global__ void pack_vt(const __half* __restrict__ ukv, __half* __restrict__ oh) {
    __shared__ __half tile[32][40];
    int t0 = blockIdx.x * 32, c0 = blockIdx.y * 32, bh = blockIdx.z;
    int b = bh >> 4, h = bh & 15;
    int tx = threadIdx.x, ty = threadIdx.y;   // 32 x 8
#pragma unroll
    for (int j = 0; j < 4; ++j) {
        int t = t0 + ty + j * 8;
        tile[ty + j * 8][tx] = ukv[((size_t)b * TSEQ + t) * 4096 + h * 256 + 128 + c0 + tx];
    }
    __syncthreads();
#pragma unroll
    for (int j = 0; j < 4; ++j) {
        int c = c0 + ty + j * 8;
        oh[((size_t)bh * DV + c) * TSEQ + t0 + tx] = tile[tx][ty + j * 8];
    }
}

// ---------------- tensor-core flash attention (single-pass fp16) ----------------
// BQ=128, BK=64, 8 warps. Q single plane; K+V double-buffered.
#define QPL  49152           // 128 rows x 384B
#define KPL  24576           // 64 x 384B
#define VPL  16384           // 128 x 128B
#define KVSTG (KPL + VPL)    // 40960
#define ATT_SMEM (QPL + 2*KVSTG)   // 131072

__global__ __launch_bounds__(256, 1) void attn_mma(
    const __half* __restrict__ qh, const __half* __restrict__ kh,
    const __half* __restrict__ vh, __half* __restrict__ outh)
{
    extern __shared__ __align__(128) char smem[];
    const uint32_t S0 = smem_u32(smem);
    const int tid = threadIdx.x, wid = tid >> 5, lane = tid & 31;
    const int qt = gridDim.x - 1 - blockIdx.x;      // heavy tiles first
    const int bh = blockIdx.y;
    const int q0 = qt * 128;
    const int nk = 2 * qt + 2;

    const size_t tbase = (size_t)bh * TSEQ * DQK;
    const size_t vbase = (size_t)bh * DV * TSEQ;

    {   // Q (group 0)
        for (int i = tid; i < 128 * 24; i += 256) {
            int row = i / 24, c = i % 24;
            uint32_t sw = (uint32_t)(row * 384 + ((c ^ (row & 7)) << 4));
            cp16(S0 + sw, qh + tbase + (size_t)(q0 + row) * DQK + c * 8);
        }
        asm volatile("cp.async.commit_group;" ::: "memory");
    }
    auto loadKV = [&](int it) {
        if (it < nk) {
            uint32_t d = S0 + QPL + (uint32_t)(it & 1) * KVSTG;
            int k0 = it * 64;
            for (int i = tid; i < 64 * 24; i += 256) {
                int row = i / 24, c = i % 24;
                uint32_t sw = (uint32_t)(row * 384 + ((c ^ (row & 7)) << 4));
                cp16(d + sw, kh + tbase + (size_t)(k0 + row) * DQK + c * 8);
            }
            uint32_t dv = d + KPL;
            for (int i = tid; i < 128 * 8; i += 256) {
                int row = i / 8, c = i % 8;
                uint32_t sw = (uint32_t)(row * 128 + ((c ^ (row & 7)) << 4));
                cp16(dv + sw, vh + vbase + (size_t)row * TSEQ + k0 + c * 8);
            }
        }
        asm volatile("cp.async.commit_group;" ::: "memory");
    };

    loadKV(0);
    loadKV(1);

    const int a_r = lane & 15, a_kh = lane >> 4;
    const int b_n = ((lane >> 4) << 3) + (lane & 7), b_kh = (lane >> 3) & 1;
    const int qrow = wid * 16 + a_r;
    const uint32_t qoff_base = S0 + qrow * 384;

    float o[16][4];
#pragma unroll
    for (int j = 0; j < 16; ++j)
#pragma unroll
        for (int q = 0; q < 4; ++q) o[j][q] = 0.f;
    float m0r = NEG_BIG, m1r = NEG_BIG, l0r = 0.f, l1r = 0.f;

    for (int it = 0; it < nk; ++it) {
        asm volatile("cp.async.wait_group 1;" ::: "memory");
        __syncthreads();

        const uint32_t Kb = S0 + QPL + (uint32_t)(it & 1) * KVSTG;
        const uint32_t Vb = Kb + KPL;

        // ---- S = Q K^T (single pass) ----
        float s[8][4];
#pragma unroll
        for (int j = 0; j < 8; ++j)
#pragma unroll
            for (int q = 0; q < 4; ++q) s[j][q] = 0.f;

#pragma unroll 4
        for (int kc = 0; kc < 12; ++kc) {
            uint32_t qa = qoff_base + ((((kc * 2 + a_kh)) ^ (qrow & 7)) << 4);
            uint32_t qf[4];
            ldm4(qf, qa);
#pragma unroll
            for (int np = 0; np < 4; ++np) {
                int krow = np * 16 + b_n;
                uint32_t ka = Kb + krow * 384 + (((kc * 2 + b_kh) ^ (krow & 7)) << 4);
                uint32_t kf[4];
                ldm4(kf, ka);
#pragma unroll
                for (int t2 = 0; t2 < 2; ++t2)
                    mma16816(s[np * 2 + t2], qf, &kf[t2 * 2]);
            }
        }

        // ---- mask (last two k-tiles only) ----
        const int k0 = it * 64;
        const int r0 = q0 + wid * 16 + (lane >> 2);
        if (it >= nk - 2) {
#pragma unroll
            for (int nt = 0; nt < 8; ++nt) {
                int kcol = k0 + nt * 8 + (lane & 3) * 2;
                if (kcol     > r0)     s[nt][0] = NEG_BIG;
                if (kcol + 1 > r0)     s[nt][1] = NEG_BIG;
                if (kcol     > r0 + 8) s[nt][2] = NEG_BIG;
                if (kcol + 1 > r0 + 8) s[nt][3] = NEG_BIG;
            }
        }

        // ---- online softmax ----
        float mx0 = NEG_BIG, mx1 = NEG_BIG;
#pragma unroll
        for (int nt = 0; nt < 8; ++nt) {
            mx0 = fmaxf(mx0, fmaxf(s[nt][0], s[nt][1]));
            mx1 = fmaxf(mx1, fmaxf(s[nt][2], s[nt][3]));
        }
        mx0 = fmaxf(mx0, __shfl_xor_sync(0xffffffffu, mx0, 1));
        mx0 = fmaxf(mx0, __shfl_xor_sync(0xffffffffu, mx0, 2));
        mx1 = fmaxf(mx1, __shfl_xor_sync(0xffffffffu, mx1, 1));
        mx1 = fmaxf(mx1, __shfl_xor_sync(0xffffffffu, mx1, 2));
        const float mn0 = fmaxf(m0r, mx0), mn1 = fmaxf(m1r, mx1);
        const float al0 = __expf(m0r - mn0), al1 = __expf(m1r - mn1);
        m0r = mn0; m1r = mn1;

        float sum0 = 0.f, sum1 = 0.f;
        uint32_t ph[4][4];
#pragma unroll
        for (int nt = 0; nt < 8; ++nt) {
            float p0 = __expf(s[nt][0] - mn0);
            float p1 = __expf(s[nt][1] - mn0);
            float p2 = __expf(s[nt][2] - mn1);
            float p3 = __expf(s[nt][3] - mn1);
            sum0 += p0 + p1;
            sum1 += p2 + p3;
            __half2 h01 = __float22half2_rn(make_float2(p0, p1));
            __half2 h23 = __float22half2_rn(make_float2(p2, p3));
            const int kc2 = nt >> 1, w2 = (nt & 1) * 2;
            ph[kc2][w2]     = *(uint32_t*)&h01;
            ph[kc2][w2 + 1] = *(uint32_t*)&h23;
        }
        sum0 += __shfl_xor_sync(0xffffffffu, sum0, 1);
        sum0 += __shfl_xor_sync(0xffffffffu, sum0, 2);
        sum1 += __shfl_xor_sync(0xffffffffu, sum1, 1);
        sum1 += __shfl_xor_sync(0xffffffffu, sum1, 2);
        l0r = l0r * al0 + sum0;
        l1r = l1r * al1 + sum1;

#pragma unroll
        for (int j = 0; j < 16; ++j) {
            o[j][0] *= al0; o[j][1] *= al0;
            o[j][2] *= al1; o[j][3] *= al1;
        }

        // ---- O += P V ----
#pragma unroll
        for (int nv = 0; nv < 8; ++nv) {
            int vrow = nv * 16 + b_n;
#pragma unroll
            for (int kc2 = 0; kc2 < 4; ++kc2) {
                uint32_t va = Vb + vrow * 128 + (((kc2 * 2 + b_kh) ^ (vrow & 7)) << 4);
                uint32_t vf[4];
                ldm4(vf, va);
#pragma unroll
                for (int t2 = 0; t2 < 2; ++t2)
                    mma16816(o[nv * 2 + t2], ph[kc2], &vf[t2 * 2]);
            }
        }
        __syncthreads();
        loadKV(it + 2);
    }

    // ---- epilogue: single fp16 ----
    const float inv0 = 1.0f / l0r, inv1 = 1.0f / l1r;
    const int b = bh >> 4, h = bh & 15;
    const int row0 = b * TSEQ + q0 + wid * 16 + (lane >> 2);
#pragma unroll
    for (int j = 0; j < 16; ++j) {
        const int col = h * 128 + j * 8 + (lane & 3) * 2;
        __half2 h2a = __float22half2_rn(make_float2(o[j][0] * inv0, o[j][1] * inv0));
        __half2 h2b = __float22half2_rn(make_float2(o[j][2] * inv1, o[j][3] * inv1));
        *(__half2*)(outh + (size_t)row0 * DM + col)       = h2a;
        *(__half2*)(outh + (size_t)(row0 + 8) * DM + col) = h2b;
    }
}

// ---------------- host-side helpers ----------------
static void run_conv(const float* src, __half* dst, size_t n) {
    int n4 = (int)(n / 4);
    conv_f16<<<(n4 + 255) / 256, 256>>>(src, dst, n4);
}
static void run_convs(const float* src, __half* dst, size_t n) {
    int n4 = (int)(n / 4);
    conv_f16s<<<(n4 + 255) / 256, 256>>>(src, dst, n4);
}
template<int BN>
static void run_gemm_f32(const __half* a, const __half* b, float* c, int M, int N, int K) {
    constexpr int SMEM = 3 * (128 * 128 + BN * 128);
    cudaFuncSetAttribute(gemm_s<BN, 0>, cudaFuncAttributeMaxDynamicSharedMemorySize, SMEM);
    gemm_s<BN, 0><<<dim3(N / BN, M / 128), 256, SMEM>>>(a, b, c, nullptr, M, N, K);
}
template<int BN>
static void run_gemm_f16(const __half* a, const __half* b, __half* c, int M, int N, int K) {
    constexpr int SMEM = 3 * (128 * 128 + BN * 128);
    cudaFuncSetAttribute(gemm_s<BN, 1>, cudaFuncAttributeMaxDynamicSharedMemorySize, SMEM);
    gemm_s<BN, 1><<<dim3(N / BN, M / 128), 256, SMEM>>>(a, b, nullptr, c, M, N, K);
}

extern "C" void kernel_launch(void* const* d_in, const int* in_sizes, int n_in,
                              void* d_out, int out_size) {
    const float* x      = (const float*)d_in[0];
    const float* w_q    = (const float*)d_in[1];
    const float* w_dkv  = (const float*)d_in[2];
    const float* w_ukv  = (const float*)d_in[3];
    const float* w_o    = (const float*)d_in[4];
    const float* w_qrot = (const float*)d_in[5];
    const float* w_krot = (const float*)d_in[6];
    float* out = (float*)d_out;

    float *p_qrot, *p_krot;
    cudaGetSymbolAddress((void**)&p_qrot, g_qrot);
    cudaGetSymbolAddress((void**)&p_krot, g_krot);
    __half *xh,*wqh,*wqrh,*wkrh,*wdh,*wuh,*woh;
    __half *p_qproj,*p_dkv,*p_ukv,*p_attn,*pqh,*pkh,*pvh;
    cudaGetSymbolAddress((void**)&xh,  g_x);
    cudaGetSymbolAddress((void**)&wqh, g_wq_h);
    cudaGetSymbolAddress((void**)&wqrh,g_wqr_h);
    cudaGetSymbolAddress((void**)&wkrh,g_wkr_h);
    cudaGetSymbolAddress((void**)&wdh, g_wdkv_h);
    cudaGetSymbolAddress((void**)&wuh, g_wukv_h);
    cudaGetSymbolAddress((void**)&woh, g_wo_h);
    cudaGetSymbolAddress((void**)&p_qproj, g_qproj);
    cudaGetSymbolAddress((void**)&p_dkv,   g_dkv);
    cudaGetSymbolAddress((void**)&p_ukv,   g_ukv);
    cudaGetSymbolAddress((void**)&p_attn,  g_attn);
    cudaGetSymbolAddress((void**)&pqh, g_qh);
    cudaGetSymbolAddress((void**)&pkh, g_kh);
    cudaGetSymbolAddress((void**)&pvh, g_vh);

    run_conv (x,      xh,   (size_t)BT * DM);              // 0
    run_convs(w_q,    wqh,  (size_t)DM * DM);              // 1 (SCALE folded)
    run_convs(w_qrot, wqrh, (size_t)1024 * DM);            // 2 (SCALE folded)
    run_gemm_f16<128>(xh, wqh, p_qproj, BT, DM, DM);       // 3  <- profiled
    run_conv (w_krot, wkrh, (size_t)64 * DM);              // 4
    run_conv (w_dkv,  wdh,  (size_t)512 * DM);             // 5
    run_conv (w_ukv,  wuh,  (size_t)4096 * 512);           // 6
    run_conv (w_o,    woh,  (size_t)DM * DM);              // 7
    run_gemm_f32<128>(xh, wqrh, p_qrot, BT, 1024, DM);     // 8
    run_gemm_f32<64> (xh, wkrh, p_krot, BT, 64,   DM);     // 9
    run_gemm_f16<128>(xh, wdh, p_dkv, BT, 512, DM);        // 10
    run_gemm_f16<128>(p_dkv, wuh, p_ukv, BT, 4096, 512);   // 11

    rope_kernel<<<(BT * 16 * 32 + 255) / 256, 256>>>(p_qrot, BT * 16, 16);
    rope_kernel<<<(BT * 32 + 255) / 256, 256>>>(p_krot, BT, 1);

    const int npk = 32 * TSEQ * 24;
    pack_q<<<npk / 256, 256>>>(p_qproj, p_qrot, pqh);
    pack_k<<<npk / 256, 256>>>(p_ukv, p_krot, pkh);
    pack_vt<<<dim3(TSEQ / 32, DV / 32, 32), dim3(32, 8)>>>(p_ukv, pvh);

    cudaFuncSetAttribute(attn_mma, cudaFuncAttributeMaxDynamicSharedMemorySize, ATT_SMEM);
    attn_mma<<<dim3(TSEQ / 128, 32), 256, ATT_SMEM>>>(pqh, pkh, pvh, p_attn);

    run_gemm_f32<128>(p_attn, woh, out, BT, DM, DM);
}

// round 8
// speedup vs baseline: 7.8243x; 1.0125x over previous
#include <cuda_runtime.h>
#include <cuda_fp16.h>
#include <math.h>
#include <cstdint>

#define BT    4096
#define TSEQ  2048
#define DM    2048
#define DQK   192
#define DV    128
#define ATT_SCALE 0.07216878364870323f   // 1/sqrt(192)
#define NEG_BIG  -1e30f

// ---------------- scratch ----------------
__device__ float  g_qrot [BT * 1024];     // fp32 (unroped, pre-scaled)
__device__ float  g_krot [BT * 64];       // fp32 (unroped)
__device__ __half g_dkv  [BT * 512];
__device__ __half g_attn [BT * DM];
__device__ __half g_x    [BT * DM];
__device__ __half g_wq_h [DM * DM];
__device__ __half g_wqr_h[1024 * DM];
__device__ __half g_wkr_h[64 * DM];
__device__ __half g_wdkv_h[512 * DM];
__device__ __half g_wukv_h[4096 * 512];
__device__ __half g_wo_h [DM * DM];
// packed attention operands
__device__ __half g_qh [32 * TSEQ * DQK];   // [bh][t][192] (scaled; cols 0-127 from gemm, 128-191 from rope)
__device__ __half g_kh [32 * TSEQ * 128];   // [bh][t][128] (from ukv gemm)
__device__ __half g_krh[ 2 * TSEQ * 64];    // [b][t][64]   (roped k_rot, shared across heads)
__device__ __half g_vh [32 * TSEQ * 128];   // [bh][t][128] (from ukv gemm)

// ---------------- PTX helpers ----------------
__device__ __forceinline__ void cp16(uint32_t s, const void* g) {
    asm volatile("cp.async.cg.shared.global [%0], [%1], 16;" :: "r"(s), "l"(g) : "memory");
}
__device__ __forceinline__ uint32_t smem_u32(const void* p) {
    uint32_t a;
    asm("{ .reg .u64 t; cvta.to.shared.u64 t, %1; cvt.u32.u64 %0, t; }" : "=r"(a) : "l"(p));
    return a;
}
__device__ __forceinline__ void ldm4(uint32_t* r, uint32_t addr) {
    asm volatile("ldmatrix.sync.aligned.m8n8.x4.shared.b16 {%0,%1,%2,%3}, [%4];"
        : "=r"(r[0]), "=r"(r[1]), "=r"(r[2]), "=r"(r[3]) : "r"(addr));
}
__device__ __forceinline__ void ldm4t(uint32_t* r, uint32_t addr) {
    asm volatile("ldmatrix.sync.aligned.m8n8.x4.trans.shared.b16 {%0,%1,%2,%3}, [%4];"
        : "=r"(r[0]), "=r"(r[1]), "=r"(r[2]), "=r"(r[3]) : "r"(addr));
}
__device__ __forceinline__ void mma16816(float* c, const uint32_t* a, const uint32_t* b) {
    asm volatile(
        "mma.sync.aligned.m16n8k16.row.col.f32.f16.f16.f32 "
        "{%0,%1,%2,%3}, {%4,%5,%6,%7}, {%8,%9}, {%0,%1,%2,%3};"
        : "+f"(c[0]), "+f"(c[1]), "+f"(c[2]), "+f"(c[3])
        : "r"(a[0]), "r"(a[1]), "r"(a[2]), "r"(a[3]), "r"(b[0]), "r"(b[1]));
}
__device__ __forceinline__ void mma16816b(float* c, const uint32_t* a, uint32_t b0, uint32_t b1) {
    asm volatile(
        "mma.sync.aligned.m16n8k16.row.col.f32.f16.f16.f32 "
        "{%0,%1,%2,%3}, {%4,%5,%6,%7}, {%8,%9}, {%0,%1,%2,%3};"
        : "+f"(c[0]), "+f"(c[1]), "+f"(c[2]), "+f"(c[3])
        : "r"(a[0]), "r"(a[1]), "r"(a[2]), "r"(a[3]), "r"(b0), "r"(b1));
}

// ---------------- fp32 -> fp16 converts ----------------
__global__ void conv_f16(const float* __restrict__ in, __half* __restrict__ out, int n4) {
    int i = blockIdx.x * blockDim.x + threadIdx.x;
    if (i >= n4) return;
    float4 v = ((const float4*)in)[i];
    ((__half2*)out)[i*2]   = __halves2half2(__float2half_rn(v.x), __float2half_rn(v.y));
    ((__half2*)out)[i*2+1] = __halves2half2(__float2half_rn(v.z), __float2half_rn(v.w));
}
__global__ void conv_f16s(const float* __restrict__ in, __half* __restrict__ out, int n4) {
    int i = blockIdx.x * blockDim.x + threadIdx.x;
    if (i >= n4) return;
    float4 v = ((const float4*)in)[i];
    ((__half2*)out)[i*2]   = __halves2half2(__float2half_rn(v.x * ATT_SCALE),
                                            __float2half_rn(v.y * ATT_SCALE));
    ((__half2*)out)[i*2+1] = __halves2half2(__float2half_rn(v.z * ATT_SCALE),
                                            __float2half_rn(v.w * ATT_SCALE));
}

// ---------------- single-pass fp16 NT GEMM, 3-stage / 1-sync pipeline ----------------
// EPI: 0 fp32 C; 1 fp16 CH [M][N]; 2 q-pack (CH = g_qh, N=2048); 3 ukv split (CH=g_kh, CH2=g_vh, N=4096)
template<int BN, int EPI>
__global__ __launch_bounds__(256, 2)
void gemm_s(const __half* __restrict__ A, const __half* __restrict__ B,
            float* __restrict__ C, __half* __restrict__ CH, __half* __restrict__ CH2,
            int M, int N, int K)
{
    constexpr int ATILE = 128 * 128;
    constexpr int BTILE = BN * 128;
    constexpr int STG   = ATILE + BTILE;
    constexpr int WN = (BN == 128) ? 4 : 2;
    constexpr int WTM = 128 / (8 / WN);
    constexpr int MT = WTM / 16;
    constexpr int NT = 4;

    extern __shared__ __align__(128) char smem[];
    const uint32_t d0 = smem_u32(smem);

    const int tid = threadIdx.x;
    const int wid = tid >> 5, lane = tid & 31;
    const int wn = wid % WN, wm = wid / WN;
    const int m0 = blockIdx.y * 128;
    const int n0 = blockIdx.x * BN;
    const int l7 = lane & 7;

    float acc[MT][NT][4];
#pragma unroll
    for (int i = 0; i < MT; ++i)
#pragma unroll
        for (int j = 0; j < NT; ++j)
#pragma unroll
            for (int q = 0; q < 4; ++q) acc[i][j][q] = 0.f;

    uint32_t arow[MT], brow[NT / 2];
    const int a_r = lane & 15;
    const int a_kh = lane >> 4;
    const int b_n = ((lane >> 4) << 3) + (lane & 7);
    const int b_kh = (lane >> 3) & 1;
#pragma unroll
    for (int mt = 0; mt < MT; ++mt) arow[mt] = (uint32_t)((wm * WTM + mt * 16 + a_r) * 128);
#pragma unroll
    for (int np = 0; np < NT / 2; ++np) brow[np] = (uint32_t)((wn * 32 + np * 16 + b_n) * 128);

    const int T = K >> 6;
    auto load_tile = [&](int t) {
        if (t < T) {
            const uint32_t d = d0 + (uint32_t)(t % 3) * STG;
            const int k0 = t * 64;
#pragma unroll
            for (int j = 0; j < 4; ++j) {
                const int c = tid + j * 256;
                const int row = c >> 3, ch = c & 7;
                const uint32_t sw = (uint32_t)(row * 128 + ((ch ^ (row & 7)) << 4));
                cp16(d + sw, A + (size_t)(m0 + row) * K + k0 + ch * 8);
            }
#pragma unroll
            for (int j = 0; j < BN / 32; ++j) {
                const int c = tid + j * 256;
                const int row = c >> 3, ch = c & 7;
                const uint32_t sw = (uint32_t)(row * 128 + ((ch ^ (row & 7)) << 4));
                cp16(d + ATILE + sw, B + (size_t)(n0 + row) * K + k0 + ch * 8);
            }
        }
        asm volatile("cp.async.commit_group;" ::: "memory");
    };

    load_tile(0);
    load_tile(1);

    for (int t = 0; t < T; ++t) {
        asm volatile("cp.async.wait_group 1;" ::: "memory");
        __syncthreads();
        load_tile(t + 2);     // writes stage (t+2)%3 == (t-1)%3: fully consumed pre-sync

        const uint32_t AS = d0 + (uint32_t)(t % 3) * STG;
        const uint32_t BS = AS + ATILE;

#pragma unroll
        for (int kk = 0; kk < 4; ++kk) {
            const uint32_t aoff = (uint32_t)(((kk * 2 + a_kh) ^ l7) << 4);
            const uint32_t boff = (uint32_t)(((kk * 2 + b_kh) ^ l7) << 4);
            uint32_t af[MT][4], bf[NT / 2][4];
#pragma unroll
            for (int mt = 0; mt < MT; ++mt)
                ldm4(af[mt], AS + arow[mt] + aoff);
#pragma unroll
            for (int np = 0; np < NT / 2; ++np)
                ldm4(bf[np], BS + brow[np] + boff);
#pragma unroll
            for (int mt = 0; mt < MT; ++mt)
#pragma unroll
                for (int nt = 0; nt < NT; ++nt)
                    mma16816(acc[mt][nt], af[mt], &bf[nt >> 1][(nt & 1) * 2]);
        }
    }

    const int cr = lane >> 2;
    const int cc = (lane & 3) * 2;
#pragma unroll
    for (int mt = 0; mt < MT; ++mt) {
        const int r0 = m0 + wm * WTM + mt * 16 + cr;
#pragma unroll
        for (int nt = 0; nt < NT; ++nt) {
            const int col = n0 + wn * 32 + nt * 8 + cc;
            if constexpr (EPI == 0) {
                *(float2*)(C + (size_t)r0 * N + col)       = make_float2(acc[mt][nt][0], acc[mt][nt][1]);
                *(float2*)(C + (size_t)(r0 + 8) * N + col) = make_float2(acc[mt][nt][2], acc[mt][nt][3]);
            } else {
#pragma unroll
                for (int hf = 0; hf < 2; ++hf) {
                    __half2 h2 = __float22half2_rn(
                        make_float2(acc[mt][nt][hf*2], acc[mt][nt][hf*2+1]));
                    const int r = r0 + hf * 8;
                    if constexpr (EPI == 1) {
                        *(__half2*)(CH + (size_t)r * N + col) = h2;
                    } else if constexpr (EPI == 2) {
                        const int b = r >> 11, t = r & 2047;
                        const int h = col >> 7, c = col & 127;
                        *(__half2*)(CH + ((size_t)((b * 16 + h) * 2048 + t)) * 192 + c) = h2;
                    } else {   // EPI == 3
                        const int b = r >> 11, t = r & 2047;
                        const int h = col >> 8, c = col & 255;
                        const size_t base = ((size_t)((b * 16 + h) * 2048 + t)) * 128;
                        if (c < 128) *(__half2*)(CH  + base + c)         = h2;
                        else         *(__half2*)(CH2 + base + (c - 128)) = h2;
                    }
                }
            }
        }
    }
}

// ---------------- fused rope + pack ----------------
__device__ __forceinline__ void rope_pair(float x1, float x2, int i, int t,
                                          float& o1, float& o2) {
    const float invf = (float)exp2(-(double)i * (13.287712379549449 / 32.0));
    const float angf = (float)t * invf;
    double sd, cd;
    sincos((double)angf, &sd, &cd);
    const float s = (float)sd, c = (float)cd;
    o1 = x1 * c - x2 * s;
    o2 = x2 * c + x1 * s;
}

// q_rot: fp32 [m][1024] (pre-scaled) -> roped fp16 into g_qh cols 128..191
__global__ void rope_pack_q(const float* __restrict__ qr, __half* __restrict__ oh) {
    int idx = blockIdx.x * blockDim.x + threadIdx.x;   // < 32*2048*32
    int i = idx & 31;
    int rest = idx >> 5;
    int bh = rest >> 11, t = rest & 2047;
    int b = bh >> 4, h = bh & 15;
    const float* base = qr + ((size_t)(b * TSEQ + t)) * 1024 + h * 64;
    float o1, o2;
    rope_pair(base[i], base[i + 32], i, t, o1, o2);
    __half* dst = oh + ((size_t)bh * TSEQ + t) * DQK + 128;
    dst[i]      = __float2half_rn(o1);
    dst[i + 32] = __float2half_rn(o2);
}

// k_rot: fp32 [m][64] -> roped fp16 g_krh [b][t][64]
__global__ void rope_pack_k(const float* __restrict__ kr, __half* __restrict__ oh) {
    int idx = blockIdx.x * blockDim.x + threadIdx.x;   // < 2*2048*32
    int i = idx & 31;
    int rest = idx >> 5;                                // b*2048 + t
    int t = rest & 2047;
    const float* base = kr + (size_t)rest * 64;
    float o1, o2;
    rope_pair(base[i], base[i + 32], i, t, o1, o2);
    __half* dst = oh + (size_t)rest * 64;
    dst[i]      = __float2half_rn(o1);
    dst[i + 32] = __float2half_rn(o2);
}

// ---------------- tensor-core flash attention ----------------
// BQ=128, BK=64, 8 warps. Q single plane; K+V triple-buffered, 1 sync/iter.
// V kept [t][dv] and loaded with ldmatrix.trans.
#define QPL  49152           // 128 rows x 384B
#define KPL  24576           // 64 x 384B
#define VPL  16384           // 64 rows x 256B
#define KVSTG (KPL + VPL)    // 40960
#define ATT_SMEM (QPL + 3*KVSTG)   // 172032

__global__ __launch_bounds__(256, 1) void attn_mma(
    const __half* __restrict__ qh, const __half* __restrict__ kh,
    const __half* __restrict__ krh, const __half* __restrict__ vh,
    __half* __restrict__ outh)
{
    extern __shared__ __align__(128) char smem[];
    const uint32_t S0 = smem_u32(smem);
    const int tid = threadIdx.x, wid = tid >> 5, lane = tid & 31;
    const int qt = gridDim.x - 1 - blockIdx.x;      // heavy tiles first
    const int bh = blockIdx.y;
    const int b = bh >> 4, h = bh & 15;
    const int q0 = qt * 128;
    const int nk = 2 * qt + 2;

    const size_t qbase = (size_t)bh * TSEQ * DQK;
    const size_t kbase = (size_t)bh * TSEQ * 128;
    const size_t rbase = (size_t)b * TSEQ * 64;

    {   // Q (group 0)
        for (int i = tid; i < 128 * 24; i += 256) {
            int row = i / 24, c = i % 24;
            uint32_t sw = (uint32_t)(row * 384 + ((c ^ (row & 7)) << 4));
            cp16(S0 + sw, qh + qbase + (size_t)(q0 + row) * DQK + c * 8);
        }
        asm volatile("cp.async.commit_group;" ::: "memory");
    }
    auto loadKV = [&](int it) {
        if (it < nk) {
            uint32_t d = S0 + QPL + (uint32_t)(it % 3) * KVSTG;
            int k0 = it * 64;
            for (int i = tid; i < 64 * 24; i += 256) {
                int row = i / 24, c = i % 24;
                uint32_t sw = (uint32_t)(row * 384 + ((c ^ (row & 7)) << 4));
                const __half* src = (c < 16)
                    ? kh  + kbase + (size_t)(k0 + row) * 128 + c * 8
                    : krh + rbase + (size_t)(k0 + row) * 64 + (c - 16) * 8;
                cp16(d + sw, src);
            }
            uint32_t dv = d + KPL;
            for (int i = tid; i < 64 * 16; i += 256) {
                int row = i >> 4, c = i & 15;
                uint32_t sw = (uint32_t)(row * 256 + (((c & 8) | ((c & 7) ^ (row & 7))) << 4));
                cp16(dv + sw, vh + kbase + (size_t)(k0 + row) * 128 + c * 8);
            }
        }
        asm volatile("cp.async.commit_group;" ::: "memory");
    };

    loadKV(0);
    loadKV(1);

    const int a_r = lane & 15, a_kh = lane >> 4;
    const int b_n = ((lane >> 4) << 3) + (lane & 7), b_kh = (lane >> 3) & 1;
    const int qrow = wid * 16 + a_r;
    const uint32_t qoff_base = S0 + qrow * 384;
    const int v_tl = lane >> 3, v_r = lane & 7;   // trans-ldmatrix lane mapping

    float o[16][4];
#pragma unroll
    for (int j = 0; j < 16; ++j)
#pragma unroll
        for (int q = 0; q < 4; ++q) o[j][q] = 0.f;
    float m0r = NEG_BIG, m1r = NEG_BIG, l0r = 0.f, l1r = 0.f;

    for (int it = 0; it < nk; ++it) {
        asm volatile("cp.async.wait_group 1;" ::: "memory");
        __syncthreads();
        loadKV(it + 2);   // writes stage (it+2)%3 == (it-1)%3: consumed pre-sync

        const uint32_t Kb = S0 + QPL + (uint32_t)(it % 3) * KVSTG;
        const uint32_t Vb = Kb + KPL;

        // ---- S = Q K^T ----
        float s[8][4];
#pragma unroll
        for (int j = 0; j < 8; ++j)
#pragma unroll
            for (int q = 0; q < 4; ++q) s[j][q] = 0.f;

#pragma unroll 4
        for (int kc = 0; kc < 12; ++kc) {
            uint32_t qa = qoff_base + ((((kc * 2 + a_kh)) ^ (qrow & 7)) << 4);
            uint32_t qf[4];
            ldm4(qf, qa);
#pragma unroll
            for (int np = 0; np < 4; ++np) {
                int krow = np * 16 + b_n;
                uint32_t ka = Kb + krow * 384 + (((kc * 2 + b_kh) ^ (krow & 7)) << 4);
                uint32_t kf[4];
                ldm4(kf, ka);
#pragma unroll
                for (int t2 = 0; t2 < 2; ++t2)
                    mma16816(s[np * 2 + t2], qf, &kf[t2 * 2]);
            }
        }

        // ---- mask (last two k-tiles only) ----
        const int k0 = it * 64;
        const int r0 = q0 + wid * 16 + (lane >> 2);
        if (it >= nk - 2) {
#pragma unroll
            for (int nt = 0; nt < 8; ++nt) {
                int kcol = k0 + nt * 8 + (lane & 3) * 2;
                if (kcol     > r0)     s[nt][0] = NEG_BIG;
                if (kcol + 1 > r0)     s[nt][1] = NEG_BIG;
                if (kcol     > r0 + 8) s[nt][2] = NEG_BIG;
                if (kcol + 1 > r0 + 8) s[nt][3] = NEG_BIG;
            }
        }

        // ---- online softmax ----
        float mx0 = NEG_BIG, mx1 = NEG_BIG;
#pragma unroll
        for (int nt = 0; nt < 8; ++nt) {
            mx0 = fmaxf(mx0, fmaxf(s[nt][0], s[nt][1]));
            mx1 = fmaxf(mx1, fmaxf(s[nt][2], s[nt][3]));
        }
        mx0 = fmaxf(mx0, __shfl_xor_sync(0xffffffffu, mx0, 1));
        mx0 = fmaxf(mx0, __shfl_xor_sync(0xffffffffu, mx0, 2));
        mx1 = fmaxf(mx1, __shfl_xor_sync(0xffffffffu, mx1, 1));
        mx1 = fmaxf(mx1, __shfl_xor_sync(0xffffffffu, mx1, 2));
        const float mn0 = fmaxf(m0r, mx0), mn1 = fmaxf(m1r, mx1);
        const float al0 = __expf(m0r - mn0), al1 = __expf(m1r - mn1);
        m0r = mn0; m1r = mn1;

        float sum0 = 0.f, sum1 = 0.f;
        uint32_t ph[4][4];
#pragma unroll
        for (int nt = 0; nt < 8; ++nt) {
            float p0 = __expf(s[nt][0] - mn0);
            float p1 = __expf(s[nt][1] - mn0);
            float p2 = __expf(s[nt][2] - mn1);
            float p3 = __expf(s[nt][3] - mn1);
            sum0 += p0 + p1;
            sum1 += p2 + p3;
            __half2 h01 = __float22half2_rn(make_float2(p0, p1));
            __half2 h23 = __float22half2_rn(make_float2(p2, p3));
            const int kc2 = nt >> 1, w2 = (nt & 1) * 2;
            ph[kc2][w2]     = *(uint32_t*)&h01;
            ph[kc2][w2 + 1] = *(uint32_t*)&h23;
        }
        sum0 += __shfl_xor_sync(0xffffffffu, sum0, 1);
        sum0 += __shfl_xor_sync(0xffffffffu, sum0, 2);
        sum1 += __shfl_xor_sync(0xffffffffu, sum1, 1);
        sum1 += __shfl_xor_sync(0xffffffffu, sum1, 2);
        l0r = l0r * al0 + sum0;
        l1r = l1r * al1 + sum1;

#pragma unroll
        for (int j = 0; j < 16; ++j) {
            o[j][0] *= al0; o[j][1] *= al0;
            o[j][2] *= al1; o[j][3] *= al1;
        }

        // ---- O += P V  (V [t][dv] via ldmatrix.trans) ----
#pragma unroll
        for (int kc = 0; kc < 4; ++kc) {
#pragma unroll
            for (int ng = 0; ng < 8; ++ng) {
                const int trow = kc * 16 + ((v_tl >> 1) << 3) + v_r;
                const int c = ng * 2 + (v_tl & 1);
                uint32_t va = Vb + trow * 256 +
                    ((uint32_t)((c & 8) | ((c & 7) ^ (trow & 7))) << 4);
                uint32_t vf[4];
                ldm4t(vf, va);
                mma16816b(o[ng * 2],     ph[kc], vf[0], vf[2]);
                mma16816b(o[ng * 2 + 1], ph[kc], vf[1], vf[3]);
            }
        }
    }

    // ---- epilogue: single fp16 ----
    const float inv0 = 1.0f / l0r, inv1 = 1.0f / l1r;
    const int row0 = b * TSEQ + q0 + wid * 16 + (lane >> 2);
#pragma unroll
    for (int j = 0; j < 16; ++j) {
        const int col = h * 128 + j * 8 + (lane & 3) * 2;
        __half2 h2a = __float22half2_rn(make_float2(o[j][0] * inv0, o[j][1] * inv0));
        __half2 h2b = __float22half2_rn(make_float2(o[j][2] * inv1, o[j][3] * inv1));
        *(__half2*)(outh + (size_t)row0 * DM + col)       = h2a;
        *(__half2*)(outh + (size_t)(row0 + 8) * DM + col) = h2b;
    }
}

// ---------------- host-side helpers ----------------
static void run_conv(const float* src, __half* dst, size_t n) {
    int n4 = (int)(n / 4);
    conv_f16<<<(n4 + 255) / 256, 256>>>(src, dst, n4);
}
static void run_convs(const float* src, __half* dst, size_t n) {
    int n4 = (int)(n / 4);
    conv_f16s<<<(n4 + 255) / 256, 256>>>(src, dst, n4);
}
template<int BN, int EPI>
static void run_gemm(const __half* a, const __half* b,
                     float* c, __half* ch, __half* ch2, int M, int N, int K) {
    constexpr int SMEM = 3 * (128 * 128 + BN * 128);
    cudaFuncSetAttribute(gemm_s<BN, EPI>, cudaFuncAttributeMaxDynamicSharedMemorySize, SMEM);
    gemm_s<BN, EPI><<<dim3(N / BN, M / 128), 256, SMEM>>>(a, b, c, ch, ch2, M, N, K);
}

extern "C" void kernel_launch(void* const* d_in, const int* in_sizes, int n_in,
                              void* d_out, int out_size) {
    const float* x      = (const float*)d_in[0];
    const float* w_q    = (const float*)d_in[1];
    const float* w_dkv  = (const float*)d_in[2];
    const float* w_ukv  = (const float*)d_in[3];
    const float* w_o    = (const float*)d_in[4];
    const float* w_qrot = (const float*)d_in[5];
    const float* w_krot = (const float*)d_in[6];
    float* out = (float*)d_out;

    float *p_qrot, *p_krot;
    cudaGetSymbolAddress((void**)&p_qrot, g_qrot);
    cudaGetSymbolAddress((void**)&p_krot, g_krot);
    __half *xh,*wqh,*wqrh,*wkrh,*wdh,*wuh,*woh;
    __half *p_dkv,*p_attn,*pqh,*pkh,*pkrh,*pvh;
    cudaGetSymbolAddress((void**)&xh,  g_x);
    cudaGetSymbolAddress((void**)&wqh, g_wq_h);
    cudaGetSymbolAddress((void**)&wqrh,g_wqr_h);
    cudaGetSymbolAddress((void**)&wkrh,g_wkr_h);
    cudaGetSymbolAddress((void**)&wdh, g_wdkv_h);
    cudaGetSymbolAddress((void**)&wuh, g_wukv_h);
    cudaGetSymbolAddress((void**)&woh, g_wo_h);
    cudaGetSymbolAddress((void**)&p_dkv,  g_dkv);
    cudaGetSymbolAddress((void**)&p_attn, g_attn);
    cudaGetSymbolAddress((void**)&pqh,  g_qh);
    cudaGetSymbolAddress((void**)&pkh,  g_kh);
    cudaGetSymbolAddress((void**)&pkrh, g_krh);
    cudaGetSymbolAddress((void**)&pvh,  g_vh);

    run_conv (x,      xh,   (size_t)BT * DM);                      // 0
    run_convs(w_q,    wqh,  (size_t)DM * DM);                      // 1 (SCALE folded)
    run_convs(w_qrot, wqrh, (size_t)1024 * DM);                    // 2 (SCALE folded)
    run_gemm<128, 2>(xh, wqh, nullptr, pqh, nullptr, BT, DM, DM);  // 3  <- profiled (q-pack)
    run_conv (w_krot, wkrh, (size_t)64 * DM);                      // 4
    run_conv (w_dkv,  wdh,  (size_t)512 * DM);                     // 5
    run_conv (w_ukv,  wuh,  (size_t)4096 * 512);                   // 6
    run_conv (w_o,    woh,  (size_t)DM * DM);                      // 7
    run_gemm<128, 0>(xh, wqrh, p_qrot, nullptr, nullptr, BT, 1024, DM);   // 8
    run_gemm<64,  0>(xh, wkrh, p_krot, nullptr, nullptr, BT, 64,   DM);   // 9
    run_gemm<128, 1>(xh, wdh, nullptr, p_dkv, nullptr, BT, 512, DM);      // 10
    run_gemm<128, 3>(p_dkv, wuh, nullptr, pkh, pvh, BT, 4096, 512);       // 11 (k/v split)

    rope_pack_q<<<(32 * TSEQ * 32) / 256, 256>>>(p_qrot, pqh);     // 12
    rope_pack_k<<<(2 * TSEQ * 32) / 256, 256>>>(p_krot, pkrh);     // 13

    cudaFuncSetAttribute(attn_mma, cudaFuncAttributeMaxDynamicSharedMemorySize, ATT_SMEM);
    attn_mma<<<dim3(TSEQ / 128, 32), 256, ATT_SMEM>>>(pqh, pkh, pkrh, pvh, p_attn);  // 14

    run_gemm<128, 0>(p_attn, woh, out, nullptr, nullptr, BT, DM, DM);     // 15
}